// round 1
// baseline (speedup 1.0000x reference)
#include <cuda_runtime.h>
#include <cstdint>
#include <cstddef>

#define SQ   2048
#define BB   2
#define NH   12
#define DH   64
#define EM   768
#define MROWS (BB*SQ)      /* 4096 */
#define NBH  (BB*NH)       /* 24   */

static __device__ __constant__ float kScale = 0.125f;  /* 1/sqrt(64) */

/* ---------------- scratch (allocation-free, module-load time) ---------------- */
__device__ float g_Q[(size_t)NBH * SQ * DH];       /* [b,h,s,d] */
__device__ float g_K[(size_t)NBH * SQ * DH];       /* combined k + kg projection */
__device__ float g_V[(size_t)NBH * SQ * DH];
__device__ float g_O[(size_t)MROWS * EM];          /* attn_out, [b,s,h*d] */
__device__ float g_scores[(size_t)NBH * SQ * SQ];  /* fallback attn buffer */

/* =====================================================================
 * proj_gemm: C = A1@W1 (+ A2@W2) + b1 (+ b2)
 * A: [4096, 768] row-major, W: [768, 768] row-major (in x out)
 * head_scatter: write C to [b,h,s,d] layout instead of [m,n]
 * 128x128 block tile, BK=8, 8x8 per-thread, 256 threads
 * ===================================================================== */
__global__ __launch_bounds__(256) void proj_gemm(
    const float* __restrict__ A1, const float* __restrict__ W1,
    const float* __restrict__ A2, const float* __restrict__ W2,
    const float* __restrict__ b1, const float* __restrict__ b2,
    float* __restrict__ C, int head_scatter)
{
    __shared__ float As[8][128];
    __shared__ float Bs[8][128];
    const int K = EM;
    int tid = threadIdx.x;
    int tx = tid & 15, ty = tid >> 4;
    int row0 = blockIdx.y * 128, col0 = blockIdx.x * 128;
    int arow = tid >> 1, acol = (tid & 1) * 4;   /* A tile 128x8: 1 float4/thread */
    int brow = tid >> 5, bcol = (tid & 31) * 4;  /* B tile 8x128: 1 float4/thread */

    float acc[8][8];
#pragma unroll
    for (int i = 0; i < 8; i++)
#pragma unroll
        for (int j = 0; j < 8; j++) acc[i][j] = 0.f;

#pragma unroll 1
    for (int pass = 0; pass < 2; ++pass) {
        const float* A = pass ? A2 : A1;
        const float* W = pass ? W2 : W1;
        if (A == nullptr) break;
#pragma unroll 1
        for (int k0 = 0; k0 < K; k0 += 8) {
            float4 av = *(const float4*)(A + (size_t)(row0 + arow) * K + k0 + acol);
            float4 bv = *(const float4*)(W + (size_t)(k0 + brow) * EM + col0 + bcol);
            __syncthreads();
            As[acol + 0][arow] = av.x; As[acol + 1][arow] = av.y;
            As[acol + 2][arow] = av.z; As[acol + 3][arow] = av.w;
            *(float4*)&Bs[brow][bcol] = bv;
            __syncthreads();
#pragma unroll
            for (int k = 0; k < 8; k++) {
                float ra[8], rb[8];
                *(float4*)(ra)     = *(float4*)&As[k][ty * 8];
                *(float4*)(ra + 4) = *(float4*)&As[k][ty * 8 + 4];
                *(float4*)(rb)     = *(float4*)&Bs[k][tx * 8];
                *(float4*)(rb + 4) = *(float4*)&Bs[k][tx * 8 + 4];
#pragma unroll
                for (int i = 0; i < 8; i++)
#pragma unroll
                    for (int j = 0; j < 8; j++)
                        acc[i][j] += ra[i] * rb[j];
            }
        }
    }

#pragma unroll
    for (int i = 0; i < 8; i++) {
        int m = row0 + ty * 8 + i;
#pragma unroll
        for (int j = 0; j < 8; j++) {
            int n = col0 + tx * 8 + j;
            float v = acc[i][j] + b1[n];
            if (b2) v += b2[n];
            if (head_scatter) {
                int b = m >> 11, s = m & (SQ - 1);
                int h = n >> 6,  d = n & (DH - 1);
                C[(((size_t)(b * NH + h)) * SQ + s) * DH + d] = v;
            } else {
                C[(size_t)m * EM + n] = v;
            }
        }
    }
}

/* =====================================================================
 * qk_gemm: scores[bh,m,n] = mask ? scale * sum_d Q[bh,m,d]*K'[bh,n,d] : -1e9
 * 128x128 tile over (m,n), K=64 (BK=8). 256 threads, 8x8 per thread.
 * ===================================================================== */
__global__ __launch_bounds__(256) void qk_gemm(
    const float* __restrict__ Q, const float* __restrict__ Kp,
    const int* __restrict__ mask, float* __restrict__ scores)
{
    __shared__ float As[8][128];
    __shared__ float Bs[8][128];
    int bh = blockIdx.z;
    int b = bh / NH;
    const float* Qh = Q  + (size_t)bh * SQ * DH;
    const float* Kh = Kp + (size_t)bh * SQ * DH;
    int tid = threadIdx.x;
    int tx = tid & 15, ty = tid >> 4;
    int m0 = blockIdx.y * 128, n0 = blockIdx.x * 128;
    int arow = tid >> 1, acol = (tid & 1) * 4;

    float acc[8][8];
#pragma unroll
    for (int i = 0; i < 8; i++)
#pragma unroll
        for (int j = 0; j < 8; j++) acc[i][j] = 0.f;

#pragma unroll 1
    for (int k0 = 0; k0 < DH; k0 += 8) {
        float4 av = *(const float4*)(Qh + (size_t)(m0 + arow) * DH + k0 + acol);
        float4 bv = *(const float4*)(Kh + (size_t)(n0 + arow) * DH + k0 + acol);
        __syncthreads();
        As[acol + 0][arow] = av.x; As[acol + 1][arow] = av.y;
        As[acol + 2][arow] = av.z; As[acol + 3][arow] = av.w;
        Bs[acol + 0][arow] = bv.x; Bs[acol + 1][arow] = bv.y;
        Bs[acol + 2][arow] = bv.z; Bs[acol + 3][arow] = bv.w;
        __syncthreads();
#pragma unroll
        for (int k = 0; k < 8; k++) {
            float ra[8], rb[8];
            *(float4*)(ra)     = *(float4*)&As[k][ty * 8];
            *(float4*)(ra + 4) = *(float4*)&As[k][ty * 8 + 4];
            *(float4*)(rb)     = *(float4*)&Bs[k][tx * 8];
            *(float4*)(rb + 4) = *(float4*)&Bs[k][tx * 8 + 4];
#pragma unroll
            for (int i = 0; i < 8; i++)
#pragma unroll
                for (int j = 0; j < 8; j++)
                    acc[i][j] += ra[i] * rb[j];
        }
    }

#pragma unroll
    for (int i = 0; i < 8; i++) {
        int m = m0 + ty * 8 + i;
        const int* mrow = mask + (size_t)b * SQ * SQ + (size_t)m * SQ;
        float* srow = scores + (size_t)bh * SQ * SQ + (size_t)m * SQ;
#pragma unroll
        for (int j = 0; j < 8; j++) {
            int n = n0 + tx * 8 + j;
            srow[n] = mrow[n] ? acc[i][j] * kScale : -1e9f;
        }
    }
}

/* =====================================================================
 * softmax_rows: in-place row softmax, row length 2048, 256 threads/row
 * ===================================================================== */
__global__ __launch_bounds__(256) void softmax_rows(float* __restrict__ attn)
{
    float* p = attn + (size_t)blockIdx.x * SQ;
    int tid = threadIdx.x;
    __shared__ float red[8];

    float v[8];
    float mx = -3.4e38f;
#pragma unroll
    for (int i = 0; i < 8; i++) { v[i] = p[tid + i * 256]; mx = fmaxf(mx, v[i]); }
#pragma unroll
    for (int o = 16; o; o >>= 1) mx = fmaxf(mx, __shfl_xor_sync(0xffffffffu, mx, o));
    if ((tid & 31) == 0) red[tid >> 5] = mx;
    __syncthreads();
    mx = red[0];
#pragma unroll
    for (int i = 1; i < 8; i++) mx = fmaxf(mx, red[i]);

    float sum = 0.f;
#pragma unroll
    for (int i = 0; i < 8; i++) { v[i] = __expf(v[i] - mx); sum += v[i]; }
#pragma unroll
    for (int o = 16; o; o >>= 1) sum += __shfl_xor_sync(0xffffffffu, sum, o);
    __syncthreads();
    if ((tid & 31) == 0) red[tid >> 5] = sum;
    __syncthreads();
    sum = 0.f;
#pragma unroll
    for (int i = 0; i < 8; i++) sum += red[i];
    float inv = 1.0f / sum;
#pragma unroll
    for (int i = 0; i < 8; i++) p[tid + i * 256] = v[i] * inv;
}

/* =====================================================================
 * av_gemm: O[b,s, h*64+d] = sum_k P[bh,s,k] * V[bh,k,d]
 * BM=128, BN=64 (all of Dh), BK=16; 256 threads, 8x4 per thread
 * ===================================================================== */
__global__ __launch_bounds__(256) void av_gemm(
    const float* __restrict__ P, const float* __restrict__ V, float* __restrict__ O)
{
    __shared__ float Ps[16][128];
    __shared__ float Vs[16][64];
    int bh = blockIdx.y;
    int b = bh / NH, h = bh % NH;
    const float* Pb = P + (size_t)bh * SQ * SQ;
    const float* Vb = V + (size_t)bh * SQ * DH;
    int tid = threadIdx.x;
    int tx = tid & 15, ty = tid >> 4;
    int m0 = blockIdx.x * 128;
    int pr = tid >> 2, pc = (tid & 3) * 4;    /* P tile 128x16: 2 float4/thread */
    int vr = tid >> 4, vc = (tid & 15) * 4;   /* V tile 16x64 : 1 float4/thread */

    float acc[8][4];
#pragma unroll
    for (int i = 0; i < 8; i++)
#pragma unroll
        for (int j = 0; j < 4; j++) acc[i][j] = 0.f;

#pragma unroll 1
    for (int k0 = 0; k0 < SQ; k0 += 16) {
        float4 p0 = *(const float4*)(Pb + (size_t)(m0 + pr)      * SQ + k0 + pc);
        float4 p1 = *(const float4*)(Pb + (size_t)(m0 + pr + 64) * SQ + k0 + pc);
        float4 vv = *(const float4*)(Vb + (size_t)(k0 + vr) * DH + vc);
        __syncthreads();
        Ps[pc + 0][pr] = p0.x; Ps[pc + 1][pr] = p0.y;
        Ps[pc + 2][pr] = p0.z; Ps[pc + 3][pr] = p0.w;
        Ps[pc + 0][pr + 64] = p1.x; Ps[pc + 1][pr + 64] = p1.y;
        Ps[pc + 2][pr + 64] = p1.z; Ps[pc + 3][pr + 64] = p1.w;
        *(float4*)&Vs[vr][vc] = vv;
        __syncthreads();
#pragma unroll
        for (int k = 0; k < 16; k++) {
            float ra[8], rb[4];
            *(float4*)(ra)     = *(float4*)&Ps[k][ty * 8];
            *(float4*)(ra + 4) = *(float4*)&Ps[k][ty * 8 + 4];
            *(float4*)(rb)     = *(float4*)&Vs[k][tx * 4];
#pragma unroll
            for (int i = 0; i < 8; i++)
#pragma unroll
                for (int j = 0; j < 4; j++)
                    acc[i][j] += ra[i] * rb[j];
        }
    }

#pragma unroll
    for (int i = 0; i < 8; i++) {
        int s = m0 + ty * 8 + i;
        float* orow = O + ((size_t)(b * SQ + s)) * EM + h * DH;
#pragma unroll
        for (int j = 0; j < 4; j++)
            orow[tx * 4 + j] = acc[i][j];
    }
}

/* ===================================================================== */
extern "C" void kernel_launch(void* const* d_in, const int* in_sizes, int n_in,
                              void* d_out, int out_size)
{
    const float* query = (const float*)d_in[0];
    const float* key   = (const float*)d_in[1];
    const float* value = (const float*)d_in[2];
    const float* kginf = (const float*)d_in[3];
    const int*   mask  = (const int*)d_in[4];
    const float* Wq  = (const float*)d_in[5];  const float* bq  = (const float*)d_in[6];
    const float* Wk  = (const float*)d_in[7];  const float* bk  = (const float*)d_in[8];
    const float* Wv  = (const float*)d_in[9];  const float* bv  = (const float*)d_in[10];
    const float* Wkg = (const float*)d_in[11]; const float* bkg = (const float*)d_in[12];
    const float* Wo  = (const float*)d_in[13]; const float* bo  = (const float*)d_in[14];

    float* gq; float* gk; float* gv; float* go; float* gs;
    cudaGetSymbolAddress((void**)&gq, g_Q);
    cudaGetSymbolAddress((void**)&gk, g_K);
    cudaGetSymbolAddress((void**)&gv, g_V);
    cudaGetSymbolAddress((void**)&go, g_O);
    cudaGetSymbolAddress((void**)&gs, g_scores);

    const long long MAIN = (long long)MROWS * EM;          /* 3,145,728   */
    const long long ATTN = (long long)NBH * SQ * SQ;       /* 100,663,296 */
    float* out = (float*)d_out;
    float* main_out;
    float* attn;
    long long osz = (long long)out_size;
    if (osz >= MAIN + ATTN)      { main_out = out; attn = out + MAIN; }
    else if (osz >= ATTN)        { attn = out; main_out = gq; }   /* attn-only output */
    else                         { main_out = out; attn = gs; }   /* main-only output */

    dim3 blk(256);
    dim3 gproj(EM / 128, MROWS / 128);       /* (6, 32)     */
    dim3 gqk(SQ / 128, SQ / 128, NBH);       /* (16,16,24)  */
    dim3 gav(SQ / 128, NBH);                 /* (16, 24)    */

    /* Q, combined K' = key@Wk + kg@Wkg + (bk+bkg), V  -> [b,h,s,d] */
    proj_gemm<<<gproj, blk>>>(query, Wq, nullptr, nullptr, bq, nullptr, gq, 1);
    proj_gemm<<<gproj, blk>>>(key,   Wk, kginf,  Wkg,     bk, bkg,     gk, 1);
    proj_gemm<<<gproj, blk>>>(value, Wv, nullptr, nullptr, bv, nullptr, gv, 1);

    /* scores (masked, scaled) -> softmax in place -> attn weights */
    qk_gemm<<<gqk, blk>>>(gq, gk, mask, attn);
    softmax_rows<<<NBH * SQ, blk>>>(attn);

    /* attn @ V -> [b,s,e], then output projection */
    av_gemm<<<gav, blk>>>(attn, gv, go);
    proj_gemm<<<gproj, blk>>>(go, Wo, nullptr, nullptr, bo, nullptr, main_out, 0);
}

// round 4
// speedup vs baseline: 2.2946x; 2.2946x over previous
#include <cuda_runtime.h>
#include <cuda_bf16.h>
#include <cstdint>
#include <cstddef>

#define SQ   2048
#define BB   2
#define NH   12
#define DH   64
#define EM   768
#define MROWS (BB*SQ)      /* 4096 */
#define NBH  (BB*NH)       /* 24   */

/* ------------- scratch (device globals, allocation-free) ------------- */
__device__ float g_Q [(size_t)NBH * SQ * DH];        /* [bh, s, d]    */
__device__ float g_K [(size_t)NBH * SQ * DH];        /* combined k+kg */
__device__ float g_Vt[(size_t)NBH * DH * SQ];        /* [bh, d, s]    */
__device__ float g_O [(size_t)MROWS * EM];           /* attn_out      */
__device__ float g_scores[(size_t)NBH * SQ * SQ];    /* fallback attn */
__device__ float g_Wt[5ull * EM * EM];               /* W^T: q,k,kg,v,o */

/* ============================ helpers ============================ */
/* error-free-ish 2-word bf16 split: x ~= hi + lo, |err| <~ 2^-18 |x| */
__device__ __forceinline__ void split2(float x, float y, uint32_t& h, uint32_t& l) {
    __nv_bfloat162 hv = __floats2bfloat162_rn(x, y);
    float rx = x - __bfloat162float(__low2bfloat16(hv));
    float ry = y - __bfloat162float(__high2bfloat16(hv));
    __nv_bfloat162 lv = __floats2bfloat162_rn(rx, ry);
    h = *reinterpret_cast<uint32_t*>(&hv);
    l = *reinterpret_cast<uint32_t*>(&lv);
}

__device__ __forceinline__ void mma_bf16(float* d, const uint32_t* a, const uint32_t* b) {
    asm volatile(
        "mma.sync.aligned.m16n8k16.row.col.f32.bf16.bf16.f32 "
        "{%0,%1,%2,%3}, {%4,%5,%6,%7}, {%8,%9}, {%0,%1,%2,%3};"
        : "+f"(d[0]), "+f"(d[1]), "+f"(d[2]), "+f"(d[3])
        : "r"(a[0]), "r"(a[1]), "r"(a[2]), "r"(a[3]), "r"(b[0]), "r"(b[1]));
}

#define SROW 20          /* smem row stride in b32 words (16 data + 4 pad) */
#define AW128 (128*SROW) /* words per 128-row hi (or lo) buffer = 2560     */
#define BW64  (64*SROW)  /* words per 64-row buffer = 1280                 */

/* load 128x32 fp32 tile (row stride ld) into 4 float4 regs per thread */
__device__ __forceinline__ void ldg_t128(const float* P, int ld, int k0, int tid, float4* v) {
#pragma unroll
    for (int p = 0; p < 4; ++p) {
        int i = tid + p * 256, r = i >> 3, c = i & 7;
        v[p] = *(const float4*)(P + (size_t)r * ld + k0 + c * 4);
    }
}
__device__ __forceinline__ void sts_t128(uint32_t* H, uint32_t* L, const float4* v, int tid) {
#pragma unroll
    for (int p = 0; p < 4; ++p) {
        int i = tid + p * 256, r = i >> 3, c = i & 7;
        uint32_t h0, l0, h1, l1;
        split2(v[p].x, v[p].y, h0, l0);
        split2(v[p].z, v[p].w, h1, l1);
        int b = r * SROW + c * 2;
        *(uint2*)&H[b] = make_uint2(h0, h1);
        *(uint2*)&L[b] = make_uint2(l0, l1);
    }
}
__device__ __forceinline__ void ldg_t64(const float* P, int ld, int k0, int tid, float4* v) {
#pragma unroll
    for (int p = 0; p < 2; ++p) {
        int i = tid + p * 256, r = i >> 3, c = i & 7;
        v[p] = *(const float4*)(P + (size_t)r * ld + k0 + c * 4);
    }
}
__device__ __forceinline__ void sts_t64(uint32_t* H, uint32_t* L, const float4* v, int tid) {
#pragma unroll
    for (int p = 0; p < 2; ++p) {
        int i = tid + p * 256, r = i >> 3, c = i & 7;
        uint32_t h0, l0, h1, l1;
        split2(v[p].x, v[p].y, h0, l0);
        split2(v[p].z, v[p].w, h1, l1);
        int b = r * SROW + c * 2;
        *(uint2*)&H[b] = make_uint2(h0, h1);
        *(uint2*)&L[b] = make_uint2(l0, l1);
    }
}

/* one BK=32 step: warp computes 32m x (NT*8)n with 3xBF16 split */
template<int NT>
__device__ __forceinline__ void compute_tile(
    float acc[][4], const uint32_t* Ah, const uint32_t* Al,
    const uint32_t* Bh, const uint32_t* Bl, int wm, int wn, int grp, int tig)
{
#pragma unroll
    for (int kc = 0; kc < 2; ++kc) {
        int kw = kc * 8 + tig;
        uint32_t aH[2][4], aL[2][4];
#pragma unroll
        for (int mt = 0; mt < 2; ++mt) {
            int r0 = wm * 32 + mt * 16 + grp;
            aH[mt][0] = Ah[r0 * SROW + kw];       aH[mt][1] = Ah[(r0 + 8) * SROW + kw];
            aH[mt][2] = Ah[r0 * SROW + kw + 4];   aH[mt][3] = Ah[(r0 + 8) * SROW + kw + 4];
            aL[mt][0] = Al[r0 * SROW + kw];       aL[mt][1] = Al[(r0 + 8) * SROW + kw];
            aL[mt][2] = Al[r0 * SROW + kw + 4];   aL[mt][3] = Al[(r0 + 8) * SROW + kw + 4];
        }
#pragma unroll
        for (int nt = 0; nt < NT; ++nt) {
            int n = wn * (NT * 8) + nt * 8 + grp;
            uint32_t bh[2], bl[2];
            bh[0] = Bh[n * SROW + kw]; bh[1] = Bh[n * SROW + kw + 4];
            bl[0] = Bl[n * SROW + kw]; bl[1] = Bl[n * SROW + kw + 4];
#pragma unroll
            for (int mt = 0; mt < 2; ++mt) {
                mma_bf16(acc[mt * NT + nt], aH[mt], bh);
                mma_bf16(acc[mt * NT + nt], aH[mt], bl);
                mma_bf16(acc[mt * NT + nt], aL[mt], bh);
            }
        }
    }
}

/* ============================================================
 * transpose_w: Wt[o][i] = W[i][o] for 5 weight matrices
 * ============================================================ */
__global__ __launch_bounds__(256) void transpose_w(
    const float* W0, const float* W1, const float* W2,
    const float* W3, const float* W4, float* out)
{
    const float* Ws[5] = {W0, W1, W2, W3, W4};
    const float* W = Ws[blockIdx.z];
    float* O = out + (size_t)blockIdx.z * EM * EM;
    __shared__ float t[32][33];
    int tx = threadIdx.x, ty = threadIdx.y;
    int x = blockIdx.x * 32 + tx;
    int y0 = blockIdx.y * 32;
    for (int i = ty; i < 32; i += 8)
        t[i][tx] = W[(size_t)(y0 + i) * EM + x];
    __syncthreads();
    int xo = blockIdx.y * 32 + tx;
    int yo0 = blockIdx.x * 32;
    for (int i = ty; i < 32; i += 8)
        O[(size_t)(yo0 + i) * EM + xo] = t[tx][i];
}

/* ============================================================
 * proj_mma: C = A1 @ Wt1^T (+ A2 @ Wt2^T) + b1 (+ b2)
 * modes: 0 = [m,n]; 1 = [bh,s,d]; 2 = [bh,d,s] (V transposed)
 * 128x128 tile, BK=32, double-buffered, 3xBF16 mma.sync
 * ============================================================ */
__global__ __launch_bounds__(256, 1) void proj_mma(
    const float* __restrict__ A1, const float* __restrict__ A2,
    const float* __restrict__ Wt1, const float* __restrict__ Wt2,
    const float* __restrict__ b1, const float* __restrict__ b2,
    float* __restrict__ C, int mode)
{
    extern __shared__ uint32_t smw[];
    const int tid = threadIdx.x, wid = tid >> 5, lid = tid & 31;
    const int n0 = blockIdx.x * 128, m0 = blockIdx.y * 128;
    const int wm = wid & 3, wn = wid >> 2, grp = lid >> 2, tig = lid & 3;
    const int STG = 4 * AW128;

    float acc[16][4];
#pragma unroll
    for (int i = 0; i < 16; ++i)
#pragma unroll
        for (int j = 0; j < 4; ++j) acc[i][j] = 0.f;

    const int CPP = EM / 32;                 /* 24 */
    const int NCH = (A2 ? 2 : 1) * CPP;

    float4 va[4], vb[4];
    ldg_t128(A1 + (size_t)m0 * EM, EM, 0, tid, va);
    ldg_t128(Wt1 + (size_t)n0 * EM, EM, 0, tid, vb);
    sts_t128(smw, smw + AW128, va, tid);
    sts_t128(smw + 2 * AW128, smw + 3 * AW128, vb, tid);
    __syncthreads();

    for (int c = 0; c < NCH; ++c) {
        uint32_t* cur = smw + (c & 1) * STG;
        uint32_t* nxt = smw + ((c + 1) & 1) * STG;
        bool more = (c + 1 < NCH);
        if (more) {
            int cn = c + 1, pass = cn / CPP, k0 = (cn % CPP) * 32;
            const float* A = pass ? A2 : A1;
            const float* W = pass ? Wt2 : Wt1;
            ldg_t128(A + (size_t)m0 * EM, EM, k0, tid, va);
            ldg_t128(W + (size_t)n0 * EM, EM, k0, tid, vb);
        }
        compute_tile<8>(acc, cur, cur + AW128, cur + 2 * AW128, cur + 3 * AW128,
                        wm, wn, grp, tig);
        if (more) {
            sts_t128(nxt, nxt + AW128, va, tid);
            sts_t128(nxt + 2 * AW128, nxt + 3 * AW128, vb, tid);
        }
        __syncthreads();
    }

    /* stage through smem for coalesced stores */
    float* Csm = (float*)smw;
    const int CS = 132;
#pragma unroll
    for (int mt = 0; mt < 2; ++mt)
#pragma unroll
        for (int nt = 0; nt < 8; ++nt) {
            int row = wm * 32 + mt * 16 + grp, col = wn * 64 + nt * 8 + tig * 2;
            float* a = acc[mt * 8 + nt];
            *(float2*)&Csm[row * CS + col]       = make_float2(a[0], a[1]);
            *(float2*)&Csm[(row + 8) * CS + col] = make_float2(a[2], a[3]);
        }
    __syncthreads();

    if (mode == 2) {
        int b = m0 >> 11;
        int sbase = m0 & (SQ - 1);
        for (int e = tid; e < 128 * 32; e += 256) {
            int col = e >> 5, sb = e & 31;
            int n = n0 + col;
            int hh = n >> 6, d = n & 63;
            float bias = b1[n];
            float4 v;
            v.x = Csm[(sb * 4 + 0) * CS + col] + bias;
            v.y = Csm[(sb * 4 + 1) * CS + col] + bias;
            v.z = Csm[(sb * 4 + 2) * CS + col] + bias;
            v.w = Csm[(sb * 4 + 3) * CS + col] + bias;
            *(float4*)(C + (((size_t)(b * NH + hh)) * DH + d) * SQ + sbase + sb * 4) = v;
        }
    } else {
        for (int e = tid; e < 128 * 32; e += 256) {
            int row = e >> 5, c4 = (e & 31) * 4;
            int m = m0 + row, n = n0 + c4;
            float4 v = *(float4*)&Csm[row * CS + c4];
            v.x += b1[n + 0]; v.y += b1[n + 1]; v.z += b1[n + 2]; v.w += b1[n + 3];
            if (b2) { v.x += b2[n + 0]; v.y += b2[n + 1]; v.z += b2[n + 2]; v.w += b2[n + 3]; }
            if (mode == 1) {
                int b = m >> 11, sA = m & (SQ - 1);
                int hh = n >> 6, d = n & 63;
                *(float4*)(C + (((size_t)(b * NH + hh)) * SQ + sA) * DH + d) = v;
            } else {
                *(float4*)(C + (size_t)m * EM + n) = v;
            }
        }
    }
}

/* ============================================================
 * qk_mma: scores = mask ? 0.125 * Q @ K'^T : -1e9   (per bh)
 * ============================================================ */
__global__ __launch_bounds__(256, 1) void qk_mma(
    const float* __restrict__ Q, const float* __restrict__ Kp,
    const int* __restrict__ mask, float* __restrict__ scores)
{
    extern __shared__ uint32_t smw[];
    const int tid = threadIdx.x, wid = tid >> 5, lid = tid & 31;
    const int n0 = blockIdx.x * 128, m0 = blockIdx.y * 128;
    const int bh = blockIdx.z, b = bh / NH;
    const int wm = wid & 3, wn = wid >> 2, grp = lid >> 2, tig = lid & 3;
    const int STG = 4 * AW128;
    const float* Qh = Q  + (size_t)bh * SQ * DH + (size_t)m0 * DH;
    const float* Kh = Kp + (size_t)bh * SQ * DH + (size_t)n0 * DH;

    float acc[16][4];
#pragma unroll
    for (int i = 0; i < 16; ++i)
#pragma unroll
        for (int j = 0; j < 4; ++j) acc[i][j] = 0.f;

    float4 va[4], vb[4];
    ldg_t128(Qh, DH, 0, tid, va);
    ldg_t128(Kh, DH, 0, tid, vb);
    sts_t128(smw, smw + AW128, va, tid);
    sts_t128(smw + 2 * AW128, smw + 3 * AW128, vb, tid);
    __syncthreads();

    for (int c = 0; c < 2; ++c) {
        uint32_t* cur = smw + (c & 1) * STG;
        uint32_t* nxt = smw + ((c + 1) & 1) * STG;
        bool more = (c == 0);
        if (more) {
            ldg_t128(Qh, DH, 32, tid, va);
            ldg_t128(Kh, DH, 32, tid, vb);
        }
        compute_tile<8>(acc, cur, cur + AW128, cur + 2 * AW128, cur + 3 * AW128,
                        wm, wn, grp, tig);
        if (more) {
            sts_t128(nxt, nxt + AW128, va, tid);
            sts_t128(nxt + 2 * AW128, nxt + 3 * AW128, vb, tid);
        }
        __syncthreads();
    }

    float* Csm = (float*)smw;
    const int CS = 132;
#pragma unroll
    for (int mt = 0; mt < 2; ++mt)
#pragma unroll
        for (int nt = 0; nt < 8; ++nt) {
            int row = wm * 32 + mt * 16 + grp, col = wn * 64 + nt * 8 + tig * 2;
            float* a = acc[mt * 8 + nt];
            *(float2*)&Csm[row * CS + col]       = make_float2(a[0], a[1]);
            *(float2*)&Csm[(row + 8) * CS + col] = make_float2(a[2], a[3]);
        }
    __syncthreads();

    const int* mb = mask + (size_t)b * SQ * SQ;
    float* sb = scores + (size_t)bh * SQ * SQ;
    for (int e = tid; e < 128 * 32; e += 256) {
        int row = e >> 5, c4 = (e & 31) * 4;
        int m = m0 + row, n = n0 + c4;
        float4 v = *(float4*)&Csm[row * CS + c4];
        int4 mk = *(const int4*)(mb + (size_t)m * SQ + n);
        v.x = mk.x ? v.x * 0.125f : -1e9f;
        v.y = mk.y ? v.y * 0.125f : -1e9f;
        v.z = mk.z ? v.z * 0.125f : -1e9f;
        v.w = mk.w ? v.w * 0.125f : -1e9f;
        *(float4*)(sb + (size_t)m * SQ + n) = v;
    }
}

/* ============================================================
 * av_mma: O[b,s,h*64+d] = P[bh,s,:] @ Vt[bh,d,:]^T
 * 128x64 tile, BK=32, K=2048, double-buffered
 * ============================================================ */
__global__ __launch_bounds__(256, 1) void av_mma(
    const float* __restrict__ P, const float* __restrict__ Vt,
    float* __restrict__ O)
{
    extern __shared__ uint32_t smw[];
    const int tid = threadIdx.x, wid = tid >> 5, lid = tid & 31;
    const int m0 = blockIdx.x * 128;
    const int bh = blockIdx.y, b = bh / NH, hh = bh % NH;
    const int wm = wid & 3, wn = wid >> 2, grp = lid >> 2, tig = lid & 3;
    const int STG = 2 * AW128 + 2 * BW64;   /* 7680 words */
    const float* Pb = P  + (size_t)bh * SQ * SQ + (size_t)m0 * SQ;
    const float* Vb = Vt + (size_t)bh * DH * SQ;

    float acc[8][4];
#pragma unroll
    for (int i = 0; i < 8; ++i)
#pragma unroll
        for (int j = 0; j < 4; ++j) acc[i][j] = 0.f;

    float4 va[4], vb2[2];
    ldg_t128(Pb, SQ, 0, tid, va);
    ldg_t64(Vb, SQ, 0, tid, vb2);
    sts_t128(smw, smw + AW128, va, tid);
    sts_t64(smw + 2 * AW128, smw + 2 * AW128 + BW64, vb2, tid);
    __syncthreads();

    const int NCH = SQ / 32;  /* 64 */
    for (int c = 0; c < NCH; ++c) {
        uint32_t* cur = smw + (c & 1) * STG;
        uint32_t* nxt = smw + ((c + 1) & 1) * STG;
        bool more = (c + 1 < NCH);
        if (more) {
            int k0 = (c + 1) * 32;
            ldg_t128(Pb, SQ, k0, tid, va);
            ldg_t64(Vb, SQ, k0, tid, vb2);
        }
        compute_tile<4>(acc, cur, cur + AW128, cur + 2 * AW128, cur + 2 * AW128 + BW64,
                        wm, wn, grp, tig);
        if (more) {
            sts_t128(nxt, nxt + AW128, va, tid);
            sts_t64(nxt + 2 * AW128, nxt + 2 * AW128 + BW64, vb2, tid);
        }
        __syncthreads();
    }

    float* Csm = (float*)smw;
    const int CS = 68;
#pragma unroll
    for (int mt = 0; mt < 2; ++mt)
#pragma unroll
        for (int nt = 0; nt < 4; ++nt) {
            int row = wm * 32 + mt * 16 + grp, col = wn * 32 + nt * 8 + tig * 2;
            float* a = acc[mt * 4 + nt];
            *(float2*)&Csm[row * CS + col]       = make_float2(a[0], a[1]);
            *(float2*)&Csm[(row + 8) * CS + col] = make_float2(a[2], a[3]);
        }
    __syncthreads();

    for (int e = tid; e < 128 * 16; e += 256) {
        int row = e >> 4, c4 = (e & 15) * 4;
        float4 v = *(float4*)&Csm[row * CS + c4];
        *(float4*)(O + ((size_t)(b * SQ) + m0 + row) * EM + hh * DH + c4) = v;
    }
}

/* ============================================================
 * softmax_rows: in-place row softmax, row length 2048
 * ============================================================ */
__global__ __launch_bounds__(256) void softmax_rows(float* __restrict__ attn)
{
    float* p = attn + (size_t)blockIdx.x * SQ;
    int tid = threadIdx.x;
    __shared__ float red[8];

    float v[8];
    float mx = -3.4e38f;
#pragma unroll
    for (int i = 0; i < 8; i++) { v[i] = p[tid + i * 256]; mx = fmaxf(mx, v[i]); }
#pragma unroll
    for (int o = 16; o; o >>= 1) mx = fmaxf(mx, __shfl_xor_sync(0xffffffffu, mx, o));
    if ((tid & 31) == 0) red[tid >> 5] = mx;
    __syncthreads();
    mx = red[0];
#pragma unroll
    for (int i = 1; i < 8; i++) mx = fmaxf(mx, red[i]);

    float sum = 0.f;
#pragma unroll
    for (int i = 0; i < 8; i++) { v[i] = __expf(v[i] - mx); sum += v[i]; }
#pragma unroll
    for (int o = 16; o; o >>= 1) sum += __shfl_xor_sync(0xffffffffu, sum, o);
    __syncthreads();
    if ((tid & 31) == 0) red[tid >> 5] = sum;
    __syncthreads();
    sum = 0.f;
#pragma unroll
    for (int i = 0; i < 8; i++) sum += red[i];
    float inv = 1.0f / sum;
#pragma unroll
    for (int i = 0; i < 8; i++) p[tid + i * 256] = v[i] * inv;
}

/* ===================================================================== */
extern "C" void kernel_launch(void* const* d_in, const int* in_sizes, int n_in,
                              void* d_out, int out_size)
{
    (void)in_sizes; (void)n_in;
    const float* query = (const float*)d_in[0];
    const float* key   = (const float*)d_in[1];
    const float* value = (const float*)d_in[2];
    const float* kginf = (const float*)d_in[3];
    const int*   mask  = (const int*)d_in[4];
    const float* Wq  = (const float*)d_in[5];  const float* bq  = (const float*)d_in[6];
    const float* Wk  = (const float*)d_in[7];  const float* bk  = (const float*)d_in[8];
    const float* Wv  = (const float*)d_in[9];  const float* bv  = (const float*)d_in[10];
    const float* Wkg = (const float*)d_in[11]; const float* bkg = (const float*)d_in[12];
    const float* Wo  = (const float*)d_in[13]; const float* bo  = (const float*)d_in[14];

    float *gq, *gk, *gvt, *go, *gs, *gwt;
    cudaGetSymbolAddress((void**)&gq,  g_Q);
    cudaGetSymbolAddress((void**)&gk,  g_K);
    cudaGetSymbolAddress((void**)&gvt, g_Vt);
    cudaGetSymbolAddress((void**)&go,  g_O);
    cudaGetSymbolAddress((void**)&gs,  g_scores);
    cudaGetSymbolAddress((void**)&gwt, g_Wt);

    const long long MAIN = (long long)MROWS * EM;
    const long long ATTN = (long long)NBH * SQ * SQ;
    float* out = (float*)d_out;
    float* main_out;
    float* attn;
    long long osz = (long long)out_size;
    if (osz >= MAIN + ATTN)      { main_out = out; attn = out + MAIN; }
    else if (osz >= ATTN)        { attn = out; main_out = gq; }
    else                         { main_out = out; attn = gs; }

    const int PJ_SMEM = 2 * 4 * AW128 * 4;                 /* 81920 */
    const int AV_SMEM = 2 * (2 * AW128 + 2 * BW64) * 4;    /* 61440 */
    cudaFuncSetAttribute(proj_mma, cudaFuncAttributeMaxDynamicSharedMemorySize, PJ_SMEM);
    cudaFuncSetAttribute(qk_mma,   cudaFuncAttributeMaxDynamicSharedMemorySize, PJ_SMEM);
    cudaFuncSetAttribute(av_mma,   cudaFuncAttributeMaxDynamicSharedMemorySize, AV_SMEM);

    float* Wt_q  = gwt + 0ull * EM * EM;
    float* Wt_k  = gwt + 1ull * EM * EM;
    float* Wt_kg = gwt + 2ull * EM * EM;
    float* Wt_v  = gwt + 3ull * EM * EM;
    float* Wt_o  = gwt + 4ull * EM * EM;

    transpose_w<<<dim3(EM/32, EM/32, 5), dim3(32, 8)>>>(Wq, Wk, Wkg, Wv, Wo, gwt);

    dim3 blk(256);
    dim3 gproj(EM / 128, MROWS / 128);       /* (6, 32)    */
    dim3 gqk(SQ / 128, SQ / 128, NBH);       /* (16,16,24) */
    dim3 gav(SQ / 128, NBH);                 /* (16, 24)   */

    proj_mma<<<gproj, blk, PJ_SMEM>>>(query, nullptr, Wt_q, nullptr, bq, nullptr, gq, 1);
    proj_mma<<<gproj, blk, PJ_SMEM>>>(key,   kginf,   Wt_k, Wt_kg,   bk, bkg,    gk, 1);
    proj_mma<<<gproj, blk, PJ_SMEM>>>(value, nullptr, Wt_v, nullptr, bv, nullptr, gvt, 2);

    qk_mma<<<gqk, blk, PJ_SMEM>>>(gq, gk, mask, attn);
    softmax_rows<<<NBH * SQ, blk>>>(attn);

    av_mma<<<gav, blk, AV_SMEM>>>(attn, gvt, go);
    proj_mma<<<gproj, blk, PJ_SMEM>>>(go, nullptr, Wt_o, nullptr, bo, nullptr, main_out, 0);
}

// round 5
// speedup vs baseline: 2.5259x; 1.1008x over previous
#include <cuda_runtime.h>
#include <cuda_bf16.h>
#include <cstdint>
#include <cstddef>

#define SQ   2048
#define BB   2
#define NH   12
#define DH   64
#define EM   768
#define MROWS (BB*SQ)      /* 4096 */
#define NBH  (BB*NH)       /* 24   */

/* ------------- scratch (device globals, allocation-free) ------------- */
__device__ float g_Q [(size_t)NBH * SQ * DH];        /* [bh, s, d]    */
__device__ float g_K [(size_t)NBH * SQ * DH];        /* combined k+kg */
__device__ float g_Vt[(size_t)NBH * DH * SQ];        /* [bh, d, s]    */
__device__ float g_O [(size_t)MROWS * EM];           /* attn_out      */
__device__ float g_scores[(size_t)NBH * SQ * SQ];    /* fallback attn */
__device__ float g_Wt[5ull * EM * EM];               /* W^T: q,k,kg,v,o */

/* ============================ helpers ============================ */
__device__ __forceinline__ void split2(float x, float y, uint32_t& h, uint32_t& l) {
    __nv_bfloat162 hv = __floats2bfloat162_rn(x, y);
    float rx = x - __bfloat162float(__low2bfloat16(hv));
    float ry = y - __bfloat162float(__high2bfloat16(hv));
    __nv_bfloat162 lv = __floats2bfloat162_rn(rx, ry);
    h = *reinterpret_cast<uint32_t*>(&hv);
    l = *reinterpret_cast<uint32_t*>(&lv);
}

__device__ __forceinline__ void mma_bf16(float* d, const uint32_t* a, const uint32_t* b) {
    asm volatile(
        "mma.sync.aligned.m16n8k16.row.col.f32.bf16.bf16.f32 "
        "{%0,%1,%2,%3}, {%4,%5,%6,%7}, {%8,%9}, {%0,%1,%2,%3};"
        : "+f"(d[0]), "+f"(d[1]), "+f"(d[2]), "+f"(d[3])
        : "r"(a[0]), "r"(a[1]), "r"(a[2]), "r"(a[3]), "r"(b[0]), "r"(b[1]));
}

#define LDMX4(r, a)                                                          \
    asm volatile("ldmatrix.sync.aligned.m8n8.x4.shared.b16 {%0,%1,%2,%3}, [%4];" \
        : "=r"((r)[0]), "=r"((r)[1]), "=r"((r)[2]), "=r"((r)[3]) : "r"(a))

#define SROW  20            /* smem row stride in b32 words (16 data + 4 pad) */
#define SROWB 80            /* bytes */
#define AW128 (128*SROW)    /* words per 128-row buffer = 2560  */
#define BW64  (64*SROW)     /* words per 64-row buffer  = 1280  */
#define A128B (128*SROWB)   /* 10240 bytes */
#define B64B  (64*SROWB)    /* 5120 bytes  */

__device__ __forceinline__ uint32_t smem_u32(const void* p) {
    return (uint32_t)__cvta_generic_to_shared(const_cast<void*>(p));
}

/* load 128x32 fp32 tile (row stride ld) into 4 float4 regs per thread */
__device__ __forceinline__ void ldg_t128(const float* P, int ld, int k0, int tid, float4* v) {
#pragma unroll
    for (int p = 0; p < 4; ++p) {
        int i = tid + p * 256, r = i >> 3, c = i & 7;
        v[p] = *(const float4*)(P + (size_t)r * ld + k0 + c * 4);
    }
}
__device__ __forceinline__ void sts_t128(uint32_t* H, uint32_t* L, const float4* v, int tid) {
#pragma unroll
    for (int p = 0; p < 4; ++p) {
        int i = tid + p * 256, r = i >> 3, c = i & 7;
        uint32_t h0, l0, h1, l1;
        split2(v[p].x, v[p].y, h0, l0);
        split2(v[p].z, v[p].w, h1, l1);
        int b = r * SROW + c * 2;
        *(uint2*)&H[b] = make_uint2(h0, h1);
        *(uint2*)&L[b] = make_uint2(l0, l1);
    }
}
__device__ __forceinline__ void ldg_t64(const float* P, int ld, int k0, int tid, float4* v) {
#pragma unroll
    for (int p = 0; p < 2; ++p) {
        int i = tid + p * 256, r = i >> 3, c = i & 7;
        v[p] = *(const float4*)(P + (size_t)r * ld + k0 + c * 4);
    }
}
__device__ __forceinline__ void sts_t64(uint32_t* H, uint32_t* L, const float4* v, int tid) {
#pragma unroll
    for (int p = 0; p < 2; ++p) {
        int i = tid + p * 256, r = i >> 3, c = i & 7;
        uint32_t h0, l0, h1, l1;
        split2(v[p].x, v[p].y, h0, l0);
        split2(v[p].z, v[p].w, h1, l1);
        int b = r * SROW + c * 2;
        *(uint2*)&H[b] = make_uint2(h0, h1);
        *(uint2*)&L[b] = make_uint2(l0, l1);
    }
}

/* one BK=32 step via ldmatrix.x4: warp computes (MT*16)m x (NT*8)n, 3xBF16 */
template<int MT, int NT>
__device__ __forceinline__ void compute_tile(
    float acc[][4], uint32_t Ah, uint32_t Al, uint32_t Bh, uint32_t Bl,
    int wm, int wn, int lid)
{
    const int arow = lid & 15;
    const int ak   = (lid >> 4) * 16;              /* bytes */
    const int brow = (lid & 7) + ((lid >> 4) & 1) * 8;
    const int bk   = ((lid >> 3) & 1) * 16;        /* bytes */
#pragma unroll
    for (int kc = 0; kc < 2; ++kc) {
        uint32_t aH[MT][4], aL[MT][4];
#pragma unroll
        for (int mt = 0; mt < MT; ++mt) {
            uint32_t off = (uint32_t)(wm * (MT * 16) + mt * 16 + arow) * SROWB + kc * 32 + ak;
            LDMX4(aH[mt], Ah + off);
            LDMX4(aL[mt], Al + off);
        }
#pragma unroll
        for (int np = 0; np < NT / 2; ++np) {
            uint32_t boff = (uint32_t)(wn * (NT * 8) + np * 16 + brow) * SROWB + kc * 32 + bk;
            uint32_t bH[4], bL[4];
            LDMX4(bH, Bh + boff);
            LDMX4(bL, Bl + boff);
#pragma unroll
            for (int half = 0; half < 2; ++half) {
                int nt = np * 2 + half;
                uint32_t* bh = bH + half * 2;
                uint32_t* bl = bL + half * 2;
#pragma unroll
                for (int mt = 0; mt < MT; ++mt) {
                    mma_bf16(acc[mt * NT + nt], aH[mt], bh);
                    mma_bf16(acc[mt * NT + nt], aH[mt], bl);
                    mma_bf16(acc[mt * NT + nt], aL[mt], bh);
                }
            }
        }
    }
}

/* ============================================================
 * transpose_w
 * ============================================================ */
__global__ __launch_bounds__(256) void transpose_w(
    const float* W0, const float* W1, const float* W2,
    const float* W3, const float* W4, float* out)
{
    const float* Ws[5] = {W0, W1, W2, W3, W4};
    const float* W = Ws[blockIdx.z];
    float* O = out + (size_t)blockIdx.z * EM * EM;
    __shared__ float t[32][33];
    int tx = threadIdx.x, ty = threadIdx.y;
    int x = blockIdx.x * 32 + tx;
    int y0 = blockIdx.y * 32;
    for (int i = ty; i < 32; i += 8)
        t[i][tx] = W[(size_t)(y0 + i) * EM + x];
    __syncthreads();
    int xo = blockIdx.y * 32 + tx;
    int yo0 = blockIdx.x * 32;
    for (int i = ty; i < 32; i += 8)
        O[(size_t)(yo0 + i) * EM + xo] = t[tx][i];
}

/* ============================================================
 * projection GEMM body (shared by fused + o-proj kernels)
 * ============================================================ */
__device__ __forceinline__ void proj_body(
    uint32_t* smw,
    const float* __restrict__ A1, const float* __restrict__ A2,
    const float* __restrict__ Wt1, const float* __restrict__ Wt2,
    const float* __restrict__ b1, const float* __restrict__ b2,
    float* __restrict__ C, int mode, int n0, int m0)
{
    const int tid = threadIdx.x, wid = tid >> 5, lid = tid & 31;
    const int wm = wid & 3, wn = wid >> 2, grp = lid >> 2, tig = lid & 3;
    const int STG = 4 * AW128;
    const uint32_t smb = smem_u32(smw);

    float acc[16][4];
#pragma unroll
    for (int i = 0; i < 16; ++i)
#pragma unroll
        for (int j = 0; j < 4; ++j) acc[i][j] = 0.f;

    const int CPP = EM / 32;
    const int NCH = (A2 ? 2 : 1) * CPP;

    float4 va[4], vb[4];
    ldg_t128(A1 + (size_t)m0 * EM, EM, 0, tid, va);
    ldg_t128(Wt1 + (size_t)n0 * EM, EM, 0, tid, vb);
    sts_t128(smw, smw + AW128, va, tid);
    sts_t128(smw + 2 * AW128, smw + 3 * AW128, vb, tid);
    __syncthreads();

    for (int c = 0; c < NCH; ++c) {
        uint32_t* nxt = smw + ((c + 1) & 1) * STG;
        uint32_t curb = smb + (uint32_t)(c & 1) * (STG * 4);
        bool more = (c + 1 < NCH);
        if (more) {
            int cn = c + 1, pass = cn / CPP, k0 = (cn % CPP) * 32;
            const float* A = pass ? A2 : A1;
            const float* W = pass ? Wt2 : Wt1;
            ldg_t128(A + (size_t)m0 * EM, EM, k0, tid, va);
            ldg_t128(W + (size_t)n0 * EM, EM, k0, tid, vb);
        }
        compute_tile<2, 8>(acc, curb, curb + A128B, curb + 2 * A128B, curb + 3 * A128B,
                           wm, wn, lid);
        if (more) {
            sts_t128(nxt, nxt + AW128, va, tid);
            sts_t128(nxt + 2 * AW128, nxt + 3 * AW128, vb, tid);
        }
        __syncthreads();
    }

    float* Csm = (float*)smw;
    const int CS = 132;
#pragma unroll
    for (int mt = 0; mt < 2; ++mt)
#pragma unroll
        for (int nt = 0; nt < 8; ++nt) {
            int row = wm * 32 + mt * 16 + grp, col = wn * 64 + nt * 8 + tig * 2;
            float* a = acc[mt * 8 + nt];
            *(float2*)&Csm[row * CS + col]       = make_float2(a[0], a[1]);
            *(float2*)&Csm[(row + 8) * CS + col] = make_float2(a[2], a[3]);
        }
    __syncthreads();

    if (mode == 2) {
        int b = m0 >> 11;
        int sbase = m0 & (SQ - 1);
        for (int e = tid; e < 128 * 32; e += 256) {
            int col = e >> 5, sb = e & 31;
            int n = n0 + col;
            int hh = n >> 6, d = n & 63;
            float bias = b1[n];
            float4 v;
            v.x = Csm[(sb * 4 + 0) * CS + col] + bias;
            v.y = Csm[(sb * 4 + 1) * CS + col] + bias;
            v.z = Csm[(sb * 4 + 2) * CS + col] + bias;
            v.w = Csm[(sb * 4 + 3) * CS + col] + bias;
            *(float4*)(C + (((size_t)(b * NH + hh)) * DH + d) * SQ + sbase + sb * 4) = v;
        }
    } else {
        for (int e = tid; e < 128 * 32; e += 256) {
            int row = e >> 5, c4 = (e & 31) * 4;
            int m = m0 + row, n = n0 + c4;
            float4 v = *(float4*)&Csm[row * CS + c4];
            v.x += b1[n + 0]; v.y += b1[n + 1]; v.z += b1[n + 2]; v.w += b1[n + 3];
            if (b2) { v.x += b2[n + 0]; v.y += b2[n + 1]; v.z += b2[n + 2]; v.w += b2[n + 3]; }
            if (mode == 1) {
                int b = m >> 11, sA = m & (SQ - 1);
                int hh = n >> 6, d = n & 63;
                *(float4*)(C + (((size_t)(b * NH + hh)) * SQ + sA) * DH + d) = v;
            } else {
                *(float4*)(C + (size_t)m * EM + n) = v;
            }
        }
    }
}

/* fused q/k/v projections: blockIdx.z selects which */
__global__ __launch_bounds__(256, 1) void proj_qkv(
    const float* __restrict__ query, const float* __restrict__ key,
    const float* __restrict__ kginf, const float* __restrict__ value,
    const float* __restrict__ Wt,     /* base of 5 transposed mats */
    const float* __restrict__ bq, const float* __restrict__ bk,
    const float* __restrict__ bkg, const float* __restrict__ bv,
    float* __restrict__ gq, float* __restrict__ gk, float* __restrict__ gvt)
{
    extern __shared__ uint32_t smw[];
    const int n0 = blockIdx.x * 128, m0 = blockIdx.y * 128;
    const float* Wt_q  = Wt + 0ull * EM * EM;
    const float* Wt_k  = Wt + 1ull * EM * EM;
    const float* Wt_kg = Wt + 2ull * EM * EM;
    const float* Wt_v  = Wt + 3ull * EM * EM;
    if (blockIdx.z == 0)
        proj_body(smw, query, nullptr, Wt_q, nullptr, bq, nullptr, gq, 1, n0, m0);
    else if (blockIdx.z == 1)
        proj_body(smw, key, kginf, Wt_k, Wt_kg, bk, bkg, gk, 1, n0, m0);
    else
        proj_body(smw, value, nullptr, Wt_v, nullptr, bv, nullptr, gvt, 2, n0, m0);
}

/* output projection */
__global__ __launch_bounds__(256, 1) void proj_o(
    const float* __restrict__ A, const float* __restrict__ Wt_o,
    const float* __restrict__ bo, float* __restrict__ C)
{
    extern __shared__ uint32_t smw[];
    proj_body(smw, A, nullptr, Wt_o, nullptr, bo, nullptr, C, 0,
              blockIdx.x * 128, blockIdx.y * 128);
}

/* ============================================================
 * qk_mma: scores = mask ? 0.125 * Q @ K'^T : -1e9   (per bh)
 * ============================================================ */
__global__ __launch_bounds__(256, 1) void qk_mma(
    const float* __restrict__ Q, const float* __restrict__ Kp,
    const int* __restrict__ mask, float* __restrict__ scores)
{
    extern __shared__ uint32_t smw[];
    const int tid = threadIdx.x, wid = tid >> 5, lid = tid & 31;
    const int n0 = blockIdx.x * 128, m0 = blockIdx.y * 128;
    const int bh = blockIdx.z, b = bh / NH;
    const int wm = wid & 3, wn = wid >> 2, grp = lid >> 2, tig = lid & 3;
    const int STG = 4 * AW128;
    const uint32_t smb = smem_u32(smw);
    const float* Qh = Q  + (size_t)bh * SQ * DH + (size_t)m0 * DH;
    const float* Kh = Kp + (size_t)bh * SQ * DH + (size_t)n0 * DH;

    float acc[16][4];
#pragma unroll
    for (int i = 0; i < 16; ++i)
#pragma unroll
        for (int j = 0; j < 4; ++j) acc[i][j] = 0.f;

    float4 va[4], vb[4];
    ldg_t128(Qh, DH, 0, tid, va);
    ldg_t128(Kh, DH, 0, tid, vb);
    sts_t128(smw, smw + AW128, va, tid);
    sts_t128(smw + 2 * AW128, smw + 3 * AW128, vb, tid);
    __syncthreads();

    for (int c = 0; c < 2; ++c) {
        uint32_t* nxt = smw + ((c + 1) & 1) * STG;
        uint32_t curb = smb + (uint32_t)(c & 1) * (STG * 4);
        bool more = (c == 0);
        if (more) {
            ldg_t128(Qh, DH, 32, tid, va);
            ldg_t128(Kh, DH, 32, tid, vb);
        }
        compute_tile<2, 8>(acc, curb, curb + A128B, curb + 2 * A128B, curb + 3 * A128B,
                           wm, wn, lid);
        if (more) {
            sts_t128(nxt, nxt + AW128, va, tid);
            sts_t128(nxt + 2 * AW128, nxt + 3 * AW128, vb, tid);
        }
        __syncthreads();
    }

    float* Csm = (float*)smw;
    const int CS = 132;
#pragma unroll
    for (int mt = 0; mt < 2; ++mt)
#pragma unroll
        for (int nt = 0; nt < 8; ++nt) {
            int row = wm * 32 + mt * 16 + grp, col = wn * 64 + nt * 8 + tig * 2;
            float* a = acc[mt * 8 + nt];
            *(float2*)&Csm[row * CS + col]       = make_float2(a[0], a[1]);
            *(float2*)&Csm[(row + 8) * CS + col] = make_float2(a[2], a[3]);
        }
    __syncthreads();

    const int* mb = mask + (size_t)b * SQ * SQ;
    float* sb = scores + (size_t)bh * SQ * SQ;
    for (int e = tid; e < 128 * 32; e += 256) {
        int row = e >> 5, c4 = (e & 31) * 4;
        int m = m0 + row, n = n0 + c4;
        float4 v = *(float4*)&Csm[row * CS + c4];
        int4 mk = *(const int4*)(mb + (size_t)m * SQ + n);
        v.x = mk.x ? v.x * 0.125f : -1e9f;
        v.y = mk.y ? v.y * 0.125f : -1e9f;
        v.z = mk.z ? v.z * 0.125f : -1e9f;
        v.w = mk.w ? v.w * 0.125f : -1e9f;
        *(float4*)(sb + (size_t)m * SQ + n) = v;
    }
}

/* ============================================================
 * av_mma: O[b,s,h*64+d] = P[bh,s,:] @ Vt[bh,d,:]^T
 * ============================================================ */
__global__ __launch_bounds__(256, 1) void av_mma(
    const float* __restrict__ P, const float* __restrict__ Vt,
    float* __restrict__ O)
{
    extern __shared__ uint32_t smw[];
    const int tid = threadIdx.x, wid = tid >> 5, lid = tid & 31;
    const int m0 = blockIdx.x * 128;
    const int bh = blockIdx.y, b = bh / NH, hh = bh % NH;
    const int wm = wid & 3, wn = wid >> 2, grp = lid >> 2, tig = lid & 3;
    const int STG = 2 * AW128 + 2 * BW64;
    const int STGB = STG * 4;
    const uint32_t smb = smem_u32(smw);
    const float* Pb = P  + (size_t)bh * SQ * SQ + (size_t)m0 * SQ;
    const float* Vb = Vt + (size_t)bh * DH * SQ;

    float acc[8][4];
#pragma unroll
    for (int i = 0; i < 8; ++i)
#pragma unroll
        for (int j = 0; j < 4; ++j) acc[i][j] = 0.f;

    float4 va[4], vb2[2];
    ldg_t128(Pb, SQ, 0, tid, va);
    ldg_t64(Vb, SQ, 0, tid, vb2);
    sts_t128(smw, smw + AW128, va, tid);
    sts_t64(smw + 2 * AW128, smw + 2 * AW128 + BW64, vb2, tid);
    __syncthreads();

    const int NCH = SQ / 32;
    for (int c = 0; c < NCH; ++c) {
        uint32_t* nxt = smw + ((c + 1) & 1) * STG;
        uint32_t curb = smb + (uint32_t)(c & 1) * STGB;
        bool more = (c + 1 < NCH);
        if (more) {
            int k0 = (c + 1) * 32;
            ldg_t128(Pb, SQ, k0, tid, va);
            ldg_t64(Vb, SQ, k0, tid, vb2);
        }
        compute_tile<2, 4>(acc, curb, curb + A128B, curb + 2 * A128B, curb + 2 * A128B + B64B,
                           wm, wn, lid);
        if (more) {
            sts_t128(nxt, nxt + AW128, va, tid);
            sts_t64(nxt + 2 * AW128, nxt + 2 * AW128 + BW64, vb2, tid);
        }
        __syncthreads();
    }

    float* Csm = (float*)smw;
    const int CS = 68;
#pragma unroll
    for (int mt = 0; mt < 2; ++mt)
#pragma unroll
        for (int nt = 0; nt < 4; ++nt) {
            int row = wm * 32 + mt * 16 + grp, col = wn * 32 + nt * 8 + tig * 2;
            float* a = acc[mt * 4 + nt];
            *(float2*)&Csm[row * CS + col]       = make_float2(a[0], a[1]);
            *(float2*)&Csm[(row + 8) * CS + col] = make_float2(a[2], a[3]);
        }
    __syncthreads();

    for (int e = tid; e < 128 * 16; e += 256) {
        int row = e >> 4, c4 = (e & 15) * 4;
        float4 v = *(float4*)&Csm[row * CS + c4];
        *(float4*)(O + ((size_t)(b * SQ) + m0 + row) * EM + hh * DH + c4) = v;
    }
}

/* ============================================================
 * softmax_rows: in-place row softmax, row length 2048 (float4)
 * ============================================================ */
__global__ __launch_bounds__(256) void softmax_rows(float* __restrict__ attn)
{
    float4* p = (float4*)(attn + (size_t)blockIdx.x * SQ);
    int tid = threadIdx.x;
    __shared__ float red[8];

    float4 v[2];
    v[0] = p[tid];
    v[1] = p[tid + 256];
    float mx = fmaxf(fmaxf(fmaxf(v[0].x, v[0].y), fmaxf(v[0].z, v[0].w)),
                     fmaxf(fmaxf(v[1].x, v[1].y), fmaxf(v[1].z, v[1].w)));
#pragma unroll
    for (int o = 16; o; o >>= 1) mx = fmaxf(mx, __shfl_xor_sync(0xffffffffu, mx, o));
    if ((tid & 31) == 0) red[tid >> 5] = mx;
    __syncthreads();
    mx = red[0];
#pragma unroll
    for (int i = 1; i < 8; i++) mx = fmaxf(mx, red[i]);

    float sum = 0.f;
#pragma unroll
    for (int i = 0; i < 2; i++) {
        v[i].x = __expf(v[i].x - mx); v[i].y = __expf(v[i].y - mx);
        v[i].z = __expf(v[i].z - mx); v[i].w = __expf(v[i].w - mx);
        sum += v[i].x + v[i].y + v[i].z + v[i].w;
    }
#pragma unroll
    for (int o = 16; o; o >>= 1) sum += __shfl_xor_sync(0xffffffffu, sum, o);
    __syncthreads();
    if ((tid & 31) == 0) red[tid >> 5] = sum;
    __syncthreads();
    sum = 0.f;
#pragma unroll
    for (int i = 0; i < 8; i++) sum += red[i];
    float inv = 1.0f / sum;
#pragma unroll
    for (int i = 0; i < 2; i++) {
        v[i].x *= inv; v[i].y *= inv; v[i].z *= inv; v[i].w *= inv;
    }
    p[tid]       = v[0];
    p[tid + 256] = v[1];
}

/* ===================================================================== */
extern "C" void kernel_launch(void* const* d_in, const int* in_sizes, int n_in,
                              void* d_out, int out_size)
{
    (void)in_sizes; (void)n_in;
    const float* query = (const float*)d_in[0];
    const float* key   = (const float*)d_in[1];
    const float* value = (const float*)d_in[2];
    const float* kginf = (const float*)d_in[3];
    const int*   mask  = (const int*)d_in[4];
    const float* Wq  = (const float*)d_in[5];  const float* bq  = (const float*)d_in[6];
    const float* Wk  = (const float*)d_in[7];  const float* bk  = (const float*)d_in[8];
    const float* Wv  = (const float*)d_in[9];  const float* bv  = (const float*)d_in[10];
    const float* Wkg = (const float*)d_in[11]; const float* bkg = (const float*)d_in[12];
    const float* Wo  = (const float*)d_in[13]; const float* bo  = (const float*)d_in[14];

    float *gq, *gk, *gvt, *go, *gs, *gwt;
    cudaGetSymbolAddress((void**)&gq,  g_Q);
    cudaGetSymbolAddress((void**)&gk,  g_K);
    cudaGetSymbolAddress((void**)&gvt, g_Vt);
    cudaGetSymbolAddress((void**)&go,  g_O);
    cudaGetSymbolAddress((void**)&gs,  g_scores);
    cudaGetSymbolAddress((void**)&gwt, g_Wt);

    const long long MAIN = (long long)MROWS * EM;
    const long long ATTN = (long long)NBH * SQ * SQ;
    float* out = (float*)d_out;
    float* main_out;
    float* attn;
    long long osz = (long long)out_size;
    if (osz >= MAIN + ATTN)      { main_out = out; attn = out + MAIN; }
    else if (osz >= ATTN)        { attn = out; main_out = gq; }
    else                         { main_out = out; attn = gs; }

    const int PJ_SMEM = 2 * 4 * AW128 * 4;                 /* 81920 */
    const int AV_SMEM = 2 * (2 * AW128 + 2 * BW64) * 4;    /* 61440 */
    cudaFuncSetAttribute(proj_qkv, cudaFuncAttributeMaxDynamicSharedMemorySize, PJ_SMEM);
    cudaFuncSetAttribute(proj_o,   cudaFuncAttributeMaxDynamicSharedMemorySize, PJ_SMEM);
    cudaFuncSetAttribute(qk_mma,   cudaFuncAttributeMaxDynamicSharedMemorySize, PJ_SMEM);
    cudaFuncSetAttribute(av_mma,   cudaFuncAttributeMaxDynamicSharedMemorySize, AV_SMEM);

    float* Wt_o = gwt + 4ull * EM * EM;

    transpose_w<<<dim3(EM/32, EM/32, 5), dim3(32, 8)>>>(Wq, Wk, Wkg, Wv, Wo, gwt);

    dim3 blk(256);
    dim3 gqkv(EM / 128, MROWS / 128, 3);     /* (6, 32, 3) */
    dim3 gprj(EM / 128, MROWS / 128);        /* (6, 32)    */
    dim3 gqk(SQ / 128, SQ / 128, NBH);       /* (16,16,24) */
    dim3 gav(SQ / 128, NBH);                 /* (16, 24)   */

    proj_qkv<<<gqkv, blk, PJ_SMEM>>>(query, key, kginf, value, gwt,
                                     bq, bk, bkg, bv, gq, gk, gvt);

    qk_mma<<<gqk, blk, PJ_SMEM>>>(gq, gk, mask, attn);
    softmax_rows<<<NBH * SQ, blk>>>(attn);

    av_mma<<<gav, blk, AV_SMEM>>>(attn, gvt, go);
    proj_o<<<gprj, blk, PJ_SMEM>>>(go, Wt_o, bo, main_out);
}

// round 6
// speedup vs baseline: 2.5722x; 1.0183x over previous
#include <cuda_runtime.h>
#include <cuda_bf16.h>
#include <cstdint>
#include <cstddef>

#define SQ   2048
#define BB   2
#define NH   12
#define DH   64
#define EM   768
#define MROWS (BB*SQ)      /* 4096 */
#define NBH  (BB*NH)       /* 24   */

/* ------------- scratch (device globals, allocation-free) ------------- */
__device__ __align__(16) __nv_bfloat16 g_Ahi[4ull*MROWS*EM];   /* q,k,kg,v inputs */
__device__ __align__(16) __nv_bfloat16 g_Alo[4ull*MROWS*EM];
__device__ __align__(16) __nv_bfloat16 g_Wthi[5ull*EM*EM];     /* W^T: q,k,kg,v,o */
__device__ __align__(16) __nv_bfloat16 g_Wtlo[5ull*EM*EM];
__device__ __align__(16) __nv_bfloat16 g_Qhi[(size_t)NBH*SQ*DH];
__device__ __align__(16) __nv_bfloat16 g_Qlo[(size_t)NBH*SQ*DH];
__device__ __align__(16) __nv_bfloat16 g_Khi[(size_t)NBH*SQ*DH];
__device__ __align__(16) __nv_bfloat16 g_Klo[(size_t)NBH*SQ*DH];
__device__ __align__(16) __nv_bfloat16 g_Vthi[(size_t)NBH*DH*SQ];  /* [bh,d,s] */
__device__ __align__(16) __nv_bfloat16 g_Vtlo[(size_t)NBH*DH*SQ];
__device__ __align__(16) __nv_bfloat16 g_Ohi[(size_t)MROWS*EM];    /* attn_out */
__device__ __align__(16) __nv_bfloat16 g_Olo[(size_t)MROWS*EM];
__device__ float g_e [(size_t)NBH*SQ*SQ];      /* unnormalized exp scores */
__device__ float g_lp[(size_t)NBH*SQ*16];      /* per-(row, ntile) partial sums */
__device__ float g_main[(size_t)MROWS*EM];     /* fallback main-out buffer */

/* ============================ helpers ============================ */
__device__ __forceinline__ void split2(float x, float y, uint32_t& h, uint32_t& l) {
    __nv_bfloat162 hv = __floats2bfloat162_rn(x, y);
    float rx = x - __bfloat162float(__low2bfloat16(hv));
    float ry = y - __bfloat162float(__high2bfloat16(hv));
    __nv_bfloat162 lv = __floats2bfloat162_rn(rx, ry);
    h = *reinterpret_cast<uint32_t*>(&hv);
    l = *reinterpret_cast<uint32_t*>(&lv);
}

__device__ __forceinline__ void mma_bf16(float* d, const uint32_t* a, const uint32_t* b) {
    asm volatile(
        "mma.sync.aligned.m16n8k16.row.col.f32.bf16.bf16.f32 "
        "{%0,%1,%2,%3}, {%4,%5,%6,%7}, {%8,%9}, {%0,%1,%2,%3};"
        : "+f"(d[0]), "+f"(d[1]), "+f"(d[2]), "+f"(d[3])
        : "r"(a[0]), "r"(a[1]), "r"(a[2]), "r"(a[3]), "r"(b[0]), "r"(b[1]));
}

#define LDMX4(r, a)                                                          \
    asm volatile("ldmatrix.sync.aligned.m8n8.x4.shared.b16 {%0,%1,%2,%3}, [%4];" \
        : "=r"((r)[0]), "=r"((r)[1]), "=r"((r)[2]), "=r"((r)[3]) : "r"(a))

__device__ __forceinline__ void cp16(uint32_t dst, const void* src) {
    asm volatile("cp.async.cg.shared.global [%0], [%1], 16;" :: "r"(dst), "l"(src));
}
#define CP_COMMIT() asm volatile("cp.async.commit_group;" ::: "memory")
#define CP_WAIT2()  asm volatile("cp.async.wait_group 2;" ::: "memory")

#define SROWB 80            /* smem row stride bytes: 64 data + 16 pad */
#define SROW  20            /* in words */
#define A128B (128*SROWB)   /* 10240 */
#define B64B  (64*SROWB)    /* 5120  */

__device__ __forceinline__ uint32_t smem_u32(const void* p) {
    return (uint32_t)__cvta_generic_to_shared(const_cast<void*>(p));
}

/* one BK=32 step via ldmatrix.x4: warp computes (MT*16)m x (NT*8)n, 3xBF16 */
template<int MT, int NT>
__device__ __forceinline__ void compute_tile(
    float acc[][4], uint32_t Ah, uint32_t Al, uint32_t Bh, uint32_t Bl,
    int wm, int wn, int lid)
{
    const int arow = lid & 15;
    const int ak   = (lid >> 4) * 16;
    const int brow = (lid & 7) + ((lid >> 4) & 1) * 8;
    const int bk   = ((lid >> 3) & 1) * 16;
#pragma unroll
    for (int kc = 0; kc < 2; ++kc) {
        uint32_t aH[MT][4], aL[MT][4];
#pragma unroll
        for (int mt = 0; mt < MT; ++mt) {
            uint32_t off = (uint32_t)(wm * (MT * 16) + mt * 16 + arow) * SROWB + kc * 32 + ak;
            LDMX4(aH[mt], Ah + off);
            LDMX4(aL[mt], Al + off);
        }
#pragma unroll
        for (int np = 0; np < NT / 2; ++np) {
            uint32_t boff = (uint32_t)(wn * (NT * 8) + np * 16 + brow) * SROWB + kc * 32 + bk;
            uint32_t bH[4], bL[4];
            LDMX4(bH, Bh + boff);
            LDMX4(bL, Bl + boff);
#pragma unroll
            for (int half = 0; half < 2; ++half) {
                int nt = np * 2 + half;
                uint32_t* bh = bH + half * 2;
                uint32_t* bl = bL + half * 2;
#pragma unroll
                for (int mt = 0; mt < MT; ++mt) {
                    mma_bf16(acc[mt * NT + nt], aH[mt], bh);
                    mma_bf16(acc[mt * NT + nt], aH[mt], bl);
                    mma_bf16(acc[mt * NT + nt], aL[mt], bh);
                }
            }
        }
    }
}

/* ============================================================
 * split_inputs: 4 activation tensors fp32 -> bf16 hi/lo
 * ============================================================ */
__global__ __launch_bounds__(256) void split_inputs(
    const float* q, const float* k, const float* kg, const float* v,
    __nv_bfloat16* hi, __nv_bfloat16* lo)
{
    const float* S;
    if (blockIdx.y == 0) S = q; else if (blockIdx.y == 1) S = k;
    else if (blockIdx.y == 2) S = kg; else S = v;
    size_t off = (size_t)blockIdx.y * MROWS * EM;
    size_t i = (size_t)blockIdx.x * 256 + threadIdx.x;   /* float4 idx */
    float4 x = ((const float4*)S)[i];
    uint32_t h0, l0, h1, l1;
    split2(x.x, x.y, h0, l0);
    split2(x.z, x.w, h1, l1);
    *(uint2*)(hi + off + i * 4) = make_uint2(h0, h1);
    *(uint2*)(lo + off + i * 4) = make_uint2(l0, l1);
}

/* ============================================================
 * transpose_w: Wt[o][i] = W[i][o], emitted as bf16 hi/lo
 * ============================================================ */
__global__ __launch_bounds__(256) void transpose_w(
    const float* W0, const float* W1, const float* W2,
    const float* W3, const float* W4,
    __nv_bfloat16* outhi, __nv_bfloat16* outlo)
{
    const float* W;
    if (blockIdx.z == 0) W = W0; else if (blockIdx.z == 1) W = W1;
    else if (blockIdx.z == 2) W = W2; else if (blockIdx.z == 3) W = W3; else W = W4;
    size_t off = (size_t)blockIdx.z * EM * EM;
    __shared__ float t[32][33];
    int tx = threadIdx.x, ty = threadIdx.y;
    int x = blockIdx.x * 32 + tx;
    int y0 = blockIdx.y * 32;
    for (int i = ty; i < 32; i += 8)
        t[i][tx] = W[(size_t)(y0 + i) * EM + x];
    __syncthreads();
    int xo = blockIdx.y * 32 + tx;
    int yo0 = blockIdx.x * 32;
    for (int i = ty; i < 32; i += 8) {
        float val = t[tx][i];
        __nv_bfloat16 h = __float2bfloat16(val);
        float r = val - __bfloat162float(h);
        size_t idx = off + (size_t)(yo0 + i) * EM + xo;
        outhi[idx] = h;
        outlo[idx] = __float2bfloat16(r);
    }
}

/* ============================================================
 * proj_body: C = A1 @ W1^T (+ A2 @ W2^T) + b1 (+ b2)
 * all operands pre-split bf16 hi/lo; cp.async 3-stage pipeline
 * mode 0: fp32 [m,n]; mode 1: bf16 hi/lo [bh,s,d]; mode 2: bf16 hi/lo [bh,d,s]
 * ============================================================ */
__device__ __forceinline__ void proj_body(
    uint32_t* smw,
    const __nv_bfloat16* A1h, const __nv_bfloat16* A1l,
    const __nv_bfloat16* A2h, const __nv_bfloat16* A2l,
    const __nv_bfloat16* W1h, const __nv_bfloat16* W1l,
    const __nv_bfloat16* W2h, const __nv_bfloat16* W2l,
    const float* b1, const float* b2,
    float* outf, __nv_bfloat16* outhi, __nv_bfloat16* outlo,
    int mode, int n0, int m0)
{
    const int tid = threadIdx.x, wid = tid >> 5, lid = tid & 31;
    const int wm = wid & 3, wn = wid >> 2, grp = lid >> 2, tig = lid & 3;
    const uint32_t smb = smem_u32(smw);
    const int LDB = EM * 2;   /* 1536 bytes per row */

    float acc[16][4];
#pragma unroll
    for (int i = 0; i < 16; ++i)
#pragma unroll
        for (int j = 0; j < 4; ++j) acc[i][j] = 0.f;

    const int CPP = EM / 32;
    const int NCH = (A2h ? 2 : 1) * CPP;

    auto issue = [&](int slot, int c) {
        int pass = (c >= CPP);
        int k0b = (c - pass * CPP) * 64;
        const char* sAh = (const char*)(pass ? A2h : A1h) + (size_t)m0 * LDB;
        const char* sAl = (const char*)(pass ? A2l : A1l) + (size_t)m0 * LDB;
        const char* sWh = (const char*)(pass ? W2h : W1h) + (size_t)n0 * LDB;
        const char* sWl = (const char*)(pass ? W2l : W1l) + (size_t)n0 * LDB;
        uint32_t base = smb + (uint32_t)slot * (4 * A128B);
#pragma unroll
        for (int it = 0; it < 8; ++it) {
            int t = tid + it * 256;
            int w = t & 511, row = w >> 2, seg = w & 3;
            const char* sp = (it >> 1) == 0 ? sAh : (it >> 1) == 1 ? sAl
                           : (it >> 1) == 2 ? sWh : sWl;
            cp16(base + (uint32_t)(it >> 1) * A128B + row * SROWB + seg * 16,
                 sp + (size_t)row * LDB + k0b + seg * 16);
        }
    };

    issue(0, 0); CP_COMMIT();
    issue(1, 1); CP_COMMIT();
    for (int c = 0; c < NCH; ++c) {
        if (c + 2 < NCH) issue((c + 2) % 3, c + 2);
        CP_COMMIT();
        CP_WAIT2();
        __syncthreads();
        uint32_t cb = smb + (uint32_t)(c % 3) * (4 * A128B);
        compute_tile<2, 8>(acc, cb, cb + A128B, cb + 2 * A128B, cb + 3 * A128B,
                           wm, wn, lid);
        __syncthreads();
    }

    /* stage through smem */
    float* Csm = (float*)smw;
    const int CS = 132;
#pragma unroll
    for (int mt = 0; mt < 2; ++mt)
#pragma unroll
        for (int nt = 0; nt < 8; ++nt) {
            int row = wm * 32 + mt * 16 + grp, col = wn * 64 + nt * 8 + tig * 2;
            float* a = acc[mt * 8 + nt];
            *(float2*)&Csm[row * CS + col]       = make_float2(a[0], a[1]);
            *(float2*)&Csm[(row + 8) * CS + col] = make_float2(a[2], a[3]);
        }
    __syncthreads();

    for (int e = tid; e < 128 * 32; e += 256) {
        int row = e >> 5, c4 = (e & 31) * 4;
        int m = m0 + row, n = n0 + c4;
        float4 v;
        if (mode == 2) {
            /* transposed gather: 4 consecutive s for one column */
            int col = e >> 5;          /* reuse mapping: col in [0,128) */
            int sb = e & 31;
            col = row; (void)col;
        }
        if (mode == 2) {
            int col = e >> 5, sb = e & 31;
            int nn = n0 + col;
            float bias = b1[nn];
            v.x = Csm[(sb * 4 + 0) * CS + col] + bias;
            v.y = Csm[(sb * 4 + 1) * CS + col] + bias;
            v.z = Csm[(sb * 4 + 2) * CS + col] + bias;
            v.w = Csm[(sb * 4 + 3) * CS + col] + bias;
            int b = m0 >> 11, sbase = m0 & (SQ - 1);
            int hh = nn >> 6, d = nn & 63;
            size_t idx = (((size_t)(b * NH + hh)) * DH + d) * SQ + sbase + sb * 4;
            uint32_t h0, l0, h1, l1;
            split2(v.x, v.y, h0, l0);
            split2(v.z, v.w, h1, l1);
            *(uint2*)(outhi + idx) = make_uint2(h0, h1);
            *(uint2*)(outlo + idx) = make_uint2(l0, l1);
        } else {
            v = *(float4*)&Csm[row * CS + c4];
            v.x += b1[n + 0]; v.y += b1[n + 1]; v.z += b1[n + 2]; v.w += b1[n + 3];
            if (b2) { v.x += b2[n + 0]; v.y += b2[n + 1]; v.z += b2[n + 2]; v.w += b2[n + 3]; }
            if (mode == 1) {
                int b = m >> 11, sA = m & (SQ - 1);
                int hh = n >> 6, d = n & 63;
                size_t idx = (((size_t)(b * NH + hh)) * SQ + sA) * DH + d;
                uint32_t h0, l0, h1, l1;
                split2(v.x, v.y, h0, l0);
                split2(v.z, v.w, h1, l1);
                *(uint2*)(outhi + idx) = make_uint2(h0, h1);
                *(uint2*)(outlo + idx) = make_uint2(l0, l1);
            } else {
                *(float4*)(outf + (size_t)m * EM + n) = v;
            }
        }
    }
}

/* fused q/k/v projections */
__global__ __launch_bounds__(256, 1) void proj_qkv(
    const __nv_bfloat16* Ahi, const __nv_bfloat16* Alo,
    const __nv_bfloat16* Whi, const __nv_bfloat16* Wlo,
    const float* bq, const float* bk, const float* bkg, const float* bv,
    __nv_bfloat16* Qhi, __nv_bfloat16* Qlo,
    __nv_bfloat16* Khi, __nv_bfloat16* Klo,
    __nv_bfloat16* Vthi, __nv_bfloat16* Vtlo)
{
    extern __shared__ uint32_t smw[];
    const int n0 = blockIdx.x * 128, m0 = blockIdx.y * 128;
    const size_t AT = (size_t)MROWS * EM, WT = (size_t)EM * EM;
    if (blockIdx.z == 0)
        proj_body(smw, Ahi, Alo, nullptr, nullptr, Whi, Wlo, nullptr, nullptr,
                  bq, nullptr, nullptr, Qhi, Qlo, 1, n0, m0);
    else if (blockIdx.z == 1)
        proj_body(smw, Ahi + AT, Alo + AT, Ahi + 2*AT, Alo + 2*AT,
                  Whi + WT, Wlo + WT, Whi + 2*WT, Wlo + 2*WT,
                  bk, bkg, nullptr, Khi, Klo, 1, n0, m0);
    else
        proj_body(smw, Ahi + 3*AT, Alo + 3*AT, nullptr, nullptr,
                  Whi + 3*WT, Wlo + 3*WT, nullptr, nullptr,
                  bv, nullptr, nullptr, Vthi, Vtlo, 2, n0, m0);
}

/* output projection */
__global__ __launch_bounds__(256, 1) void proj_o(
    const __nv_bfloat16* Ohi, const __nv_bfloat16* Olo,
    const __nv_bfloat16* Whi, const __nv_bfloat16* Wlo,
    const float* bo, float* C)
{
    extern __shared__ uint32_t smw[];
    const size_t WT = (size_t)EM * EM;
    proj_body(smw, Ohi, Olo, nullptr, nullptr, Whi + 4*WT, Wlo + 4*WT,
              nullptr, nullptr, bo, nullptr, C, nullptr, nullptr, 0,
              blockIdx.x * 128, blockIdx.y * 128);
}

/* ============================================================
 * qk_mma: e = mask ? exp(0.125 * Q.K') : 0 ; per-(row,ntile) sums
 * ============================================================ */
__global__ __launch_bounds__(256, 1) void qk_mma(
    const __nv_bfloat16* Qhi, const __nv_bfloat16* Qlo,
    const __nv_bfloat16* Khi, const __nv_bfloat16* Klo,
    const int* __restrict__ mask, float* __restrict__ e_out,
    float* __restrict__ lp)
{
    extern __shared__ uint32_t smw[];
    const int tid = threadIdx.x, wid = tid >> 5, lid = tid & 31;
    const int n0 = blockIdx.x * 128, m0 = blockIdx.y * 128;
    const int bh = blockIdx.z, b = bh / NH;
    const int wm = wid & 3, wn = wid >> 2, grp = lid >> 2, tig = lid & 3;
    const uint32_t smb = smem_u32(smw);
    const int LDB = DH * 2;   /* 128 bytes per row */
    const char* sQh = (const char*)Qhi + ((size_t)bh * SQ + m0) * LDB;
    const char* sQl = (const char*)Qlo + ((size_t)bh * SQ + m0) * LDB;
    const char* sKh = (const char*)Khi + ((size_t)bh * SQ + n0) * LDB;
    const char* sKl = (const char*)Klo + ((size_t)bh * SQ + n0) * LDB;

    float acc[16][4];
#pragma unroll
    for (int i = 0; i < 16; ++i)
#pragma unroll
        for (int j = 0; j < 4; ++j) acc[i][j] = 0.f;

    auto issue = [&](int slot, int c) {
        int k0b = c * 64;
        uint32_t base = smb + (uint32_t)slot * (4 * A128B);
#pragma unroll
        for (int it = 0; it < 8; ++it) {
            int t = tid + it * 256;
            int w = t & 511, row = w >> 2, seg = w & 3;
            const char* sp = (it >> 1) == 0 ? sQh : (it >> 1) == 1 ? sQl
                           : (it >> 1) == 2 ? sKh : sKl;
            cp16(base + (uint32_t)(it >> 1) * A128B + row * SROWB + seg * 16,
                 sp + (size_t)row * LDB + k0b + seg * 16);
        }
    };

    issue(0, 0); CP_COMMIT();
    issue(1, 1); CP_COMMIT();
    for (int c = 0; c < 2; ++c) {
        CP_COMMIT();
        CP_WAIT2();
        __syncthreads();
        uint32_t cb = smb + (uint32_t)c * (4 * A128B);
        compute_tile<2, 8>(acc, cb, cb + A128B, cb + 2 * A128B, cb + 3 * A128B,
                           wm, wn, lid);
        __syncthreads();
    }

    float* Csm = (float*)smw;
    const int CS = 132;
#pragma unroll
    for (int mt = 0; mt < 2; ++mt)
#pragma unroll
        for (int nt = 0; nt < 8; ++nt) {
            int row = wm * 32 + mt * 16 + grp, col = wn * 64 + nt * 8 + tig * 2;
            float* a = acc[mt * 8 + nt];
            *(float2*)&Csm[row * CS + col]       = make_float2(a[0], a[1]);
            *(float2*)&Csm[(row + 8) * CS + col] = make_float2(a[2], a[3]);
        }
    __syncthreads();

    const int* mb = mask + (size_t)b * SQ * SQ;
    float* eb = e_out + (size_t)bh * SQ * SQ;
#pragma unroll 1
    for (int it = 0; it < 16; ++it) {
        int eidx = tid + it * 256;
        int row = eidx >> 5, c4 = (eidx & 31) * 4;
        int m = m0 + row, n = n0 + c4;
        float4 v = *(float4*)&Csm[row * CS + c4];
        int4 mk = *(const int4*)(mb + (size_t)m * SQ + n);
        v.x = mk.x ? __expf(v.x * 0.125f) : 0.f;
        v.y = mk.y ? __expf(v.y * 0.125f) : 0.f;
        v.z = mk.z ? __expf(v.z * 0.125f) : 0.f;
        v.w = mk.w ? __expf(v.w * 0.125f) : 0.f;
        *(float4*)(eb + (size_t)m * SQ + n) = v;
        float s4 = v.x + v.y + v.z + v.w;
#pragma unroll
        for (int o = 16; o; o >>= 1) s4 += __shfl_xor_sync(0xffffffffu, s4, o);
        if (lid == 0)
            lp[((size_t)bh * SQ + m) * 16 + blockIdx.x] = s4;
    }
}

/* ============================================================
 * av_mma: attn = e/l (written here); O = attn @ V
 * P fp32 from e buffer (normalize+split in-loop); V pre-split bf16
 * ============================================================ */
__device__ __forceinline__ void ldg_p(const float* P, int k0, int tid, float4* v) {
#pragma unroll
    for (int p = 0; p < 4; ++p) {
        int i = tid + p * 256, r = i >> 3, c = i & 7;
        v[p] = *(const float4*)(P + (size_t)r * SQ + k0 + c * 4);
    }
}

__global__ __launch_bounds__(256, 1) void av_mma(
    const float* __restrict__ e_in, const float* __restrict__ lp,
    const __nv_bfloat16* Vhi, const __nv_bfloat16* Vlo,
    float* __restrict__ attn, __nv_bfloat16* Ohi, __nv_bfloat16* Olo)
{
    extern __shared__ uint32_t smw[];
    const int tid = threadIdx.x, wid = tid >> 5, lid = tid & 31;
    const int m0 = blockIdx.x * 128;
    const int bh = blockIdx.y, b = bh / NH, hh = bh % NH;
    const int wm = wid & 3, wn = wid >> 2, grp = lid >> 2, tig = lid & 3;
    const uint32_t smb = smem_u32(smw);
    const int STGB = 2 * A128B + 2 * B64B;   /* 30720 */
    const float* Pb = e_in + (size_t)bh * SQ * SQ + (size_t)m0 * SQ;
    float* attnb = attn + (size_t)bh * SQ * SQ + (size_t)m0 * SQ;
    const char* Vh = (const char*)Vhi + (size_t)bh * DH * SQ * 2;
    const char* Vl = (const char*)Vlo + (size_t)bh * DH * SQ * 2;
    float* invl = (float*)((char*)smw + 2 * STGB);

    if (tid < 128) {
        const float* q = lp + ((size_t)bh * SQ + m0 + tid) * 16;
        float s = 0.f;
#pragma unroll
        for (int i = 0; i < 16; ++i) s += q[i];
        invl[tid] = 1.f / fmaxf(s, 1e-30f);
    }
    __syncthreads();

    float acc[8][4];
#pragma unroll
    for (int i = 0; i < 8; ++i)
#pragma unroll
        for (int j = 0; j < 4; ++j) acc[i][j] = 0.f;

    const int vrow = tid >> 2, vseg = tid & 3;

    /* store prefetched P chunk: normalize, write attn, split to smem */
    auto stsP = [&](int slot, const float4* v, int k0) {
        uint32_t* H = smw + slot * (STGB / 4);
        uint32_t* L = H + A128B / 4;
#pragma unroll
        for (int p = 0; p < 4; ++p) {
            int i = tid + p * 256, r = i >> 3, c = i & 7;
            float il = invl[r];
            float4 w;
            w.x = v[p].x * il; w.y = v[p].y * il;
            w.z = v[p].z * il; w.w = v[p].w * il;
            *(float4*)(attnb + (size_t)r * SQ + k0 + c * 4) = w;
            uint32_t h0, l0, h1, l1;
            split2(w.x, w.y, h0, l0);
            split2(w.z, w.w, h1, l1);
            int bw = r * SROW + c * 2;
            *(uint2*)&H[bw] = make_uint2(h0, h1);
            *(uint2*)&L[bw] = make_uint2(l0, l1);
        }
    };
    auto stsV = [&](int slot, uint4 vh, uint4 vl) {
        char* base = (char*)smw + slot * STGB + 2 * A128B;
        *(uint4*)(base + vrow * SROWB + vseg * 16) = vh;
        *(uint4*)(base + B64B + vrow * SROWB + vseg * 16) = vl;
    };
    auto ldgV = [&](int k0b, uint4& h, uint4& l) {
        size_t o = (size_t)vrow * (SQ * 2) + k0b + vseg * 16;
        h = *(const uint4*)(Vh + o);
        l = *(const uint4*)(Vl + o);
    };

    float4 va[4];
    uint4 vh, vl;
    ldg_p(Pb, 0, tid, va);
    ldgV(0, vh, vl);
    stsP(0, va, 0);
    stsV(0, vh, vl);
    __syncthreads();

    const int NCH = SQ / 32;   /* 64 */
    for (int c = 0; c < NCH; ++c) {
        bool more = (c + 1 < NCH);
        if (more) {
            ldg_p(Pb, (c + 1) * 32, tid, va);
            ldgV((c + 1) * 64, vh, vl);
        }
        uint32_t cb = smb + (uint32_t)(c & 1) * STGB;
        compute_tile<2, 4>(acc, cb, cb + A128B, cb + 2 * A128B, cb + 2 * A128B + B64B,
                           wm, wn, lid);
        if (more) {
            stsP((c + 1) & 1, va, (c + 1) * 32);
            stsV((c + 1) & 1, vh, vl);
        }
        __syncthreads();
    }

    float* Csm = (float*)smw;
    const int CS = 68;
#pragma unroll
    for (int mt = 0; mt < 2; ++mt)
#pragma unroll
        for (int nt = 0; nt < 4; ++nt) {
            int row = wm * 32 + mt * 16 + grp, col = wn * 32 + nt * 8 + tig * 2;
            float* a = acc[mt * 4 + nt];
            *(float2*)&Csm[row * CS + col]       = make_float2(a[0], a[1]);
            *(float2*)&Csm[(row + 8) * CS + col] = make_float2(a[2], a[3]);
        }
    __syncthreads();

    for (int e = tid; e < 128 * 16; e += 256) {
        int row = e >> 4, c4 = (e & 15) * 4;
        float4 v = *(float4*)&Csm[row * CS + c4];
        size_t idx = (size_t)(b * SQ + m0 + row) * EM + hh * DH + c4;
        uint32_t h0, l0, h1, l1;
        split2(v.x, v.y, h0, l0);
        split2(v.z, v.w, h1, l1);
        *(uint2*)(Ohi + idx) = make_uint2(h0, h1);
        *(uint2*)(Olo + idx) = make_uint2(l0, l1);
    }
}

/* ===================================================================== */
extern "C" void kernel_launch(void* const* d_in, const int* in_sizes, int n_in,
                              void* d_out, int out_size)
{
    (void)in_sizes; (void)n_in;
    const float* query = (const float*)d_in[0];
    const float* key   = (const float*)d_in[1];
    const float* value = (const float*)d_in[2];
    const float* kginf = (const float*)d_in[3];
    const int*   mask  = (const int*)d_in[4];
    const float* Wq  = (const float*)d_in[5];  const float* bq  = (const float*)d_in[6];
    const float* Wk  = (const float*)d_in[7];  const float* bk  = (const float*)d_in[8];
    const float* Wv  = (const float*)d_in[9];  const float* bv  = (const float*)d_in[10];
    const float* Wkg = (const float*)d_in[11]; const float* bkg = (const float*)d_in[12];
    const float* Wo  = (const float*)d_in[13]; const float* bo  = (const float*)d_in[14];

    __nv_bfloat16 *ahi, *alo, *whi, *wlo, *qhi, *qlo, *khi, *klo, *vthi, *vtlo, *ohi, *olo;
    float *ge, *glp, *gmain;
    cudaGetSymbolAddress((void**)&ahi,  g_Ahi);
    cudaGetSymbolAddress((void**)&alo,  g_Alo);
    cudaGetSymbolAddress((void**)&whi,  g_Wthi);
    cudaGetSymbolAddress((void**)&wlo,  g_Wtlo);
    cudaGetSymbolAddress((void**)&qhi,  g_Qhi);
    cudaGetSymbolAddress((void**)&qlo,  g_Qlo);
    cudaGetSymbolAddress((void**)&khi,  g_Khi);
    cudaGetSymbolAddress((void**)&klo,  g_Klo);
    cudaGetSymbolAddress((void**)&vthi, g_Vthi);
    cudaGetSymbolAddress((void**)&vtlo, g_Vtlo);
    cudaGetSymbolAddress((void**)&ohi,  g_Ohi);
    cudaGetSymbolAddress((void**)&olo,  g_Olo);
    cudaGetSymbolAddress((void**)&ge,   g_e);
    cudaGetSymbolAddress((void**)&glp,  g_lp);
    cudaGetSymbolAddress((void**)&gmain, g_main);

    const long long MAIN = (long long)MROWS * EM;
    const long long ATTN = (long long)NBH * SQ * SQ;
    float* out = (float*)d_out;
    float* main_out;
    float* attn;
    long long osz = (long long)out_size;
    if (osz >= MAIN + ATTN)      { main_out = out; attn = out + MAIN; }
    else if (osz >= ATTN)        { attn = out; main_out = gmain; }
    else                         { main_out = out; attn = ge; }   /* in-place ok */

    const int PJ_SMEM = 3 * 4 * A128B;                 /* 122880 */
    const int QK_SMEM = 2 * 4 * A128B;                 /* 81920  */
    const int AV_SMEM = 2 * (2 * A128B + 2 * B64B) + 512;  /* 61952 */
    cudaFuncSetAttribute(proj_qkv, cudaFuncAttributeMaxDynamicSharedMemorySize, PJ_SMEM);
    cudaFuncSetAttribute(proj_o,   cudaFuncAttributeMaxDynamicSharedMemorySize, PJ_SMEM);
    cudaFuncSetAttribute(qk_mma,   cudaFuncAttributeMaxDynamicSharedMemorySize, QK_SMEM);
    cudaFuncSetAttribute(av_mma,   cudaFuncAttributeMaxDynamicSharedMemorySize, AV_SMEM);

    dim3 blk(256);
    split_inputs<<<dim3(MROWS * EM / 4 / 256, 4), blk>>>(query, key, kginf, value, ahi, alo);
    transpose_w<<<dim3(EM/32, EM/32, 5), dim3(32, 8)>>>(Wq, Wk, Wkg, Wv, Wo, whi, wlo);

    proj_qkv<<<dim3(EM/128, MROWS/128, 3), blk, PJ_SMEM>>>(
        ahi, alo, whi, wlo, bq, bk, bkg, bv, qhi, qlo, khi, klo, vthi, vtlo);

    qk_mma<<<dim3(SQ/128, SQ/128, NBH), blk, QK_SMEM>>>(
        qhi, qlo, khi, klo, mask, ge, glp);

    av_mma<<<dim3(SQ/128, NBH), blk, AV_SMEM>>>(
        ge, glp, vthi, vtlo, attn, ohi, olo);

    proj_o<<<dim3(EM/128, MROWS/128), blk, PJ_SMEM>>>(ohi, olo, whi, wlo, bo, main_out);
}

// round 7
// speedup vs baseline: 3.0783x; 1.1968x over previous
#include <cuda_runtime.h>
#include <cuda_bf16.h>
#include <cstdint>
#include <cstddef>

#define SQ   2048
#define BB   2
#define NH   12
#define DH   64
#define EM   768
#define MROWS (BB*SQ)      /* 4096 */
#define NBH  (BB*NH)       /* 24   */

/* ------------- scratch (device globals, allocation-free) ------------- */
__device__ __align__(16) __nv_bfloat16 g_Ahi[4ull*MROWS*EM];
__device__ __align__(16) __nv_bfloat16 g_Alo[4ull*MROWS*EM];
__device__ __align__(16) __nv_bfloat16 g_Wthi[5ull*EM*EM];
__device__ __align__(16) __nv_bfloat16 g_Wtlo[5ull*EM*EM];
__device__ __align__(16) __nv_bfloat16 g_Qhi[(size_t)NBH*SQ*DH];
__device__ __align__(16) __nv_bfloat16 g_Qlo[(size_t)NBH*SQ*DH];
__device__ __align__(16) __nv_bfloat16 g_Khi[(size_t)NBH*SQ*DH];
__device__ __align__(16) __nv_bfloat16 g_Klo[(size_t)NBH*SQ*DH];
__device__ __align__(16) __nv_bfloat16 g_Vthi[(size_t)NBH*DH*SQ];
__device__ __align__(16) __nv_bfloat16 g_Vtlo[(size_t)NBH*DH*SQ];
__device__ __align__(16) __nv_bfloat16 g_Ohi[(size_t)MROWS*EM];
__device__ __align__(16) __nv_bfloat16 g_Olo[(size_t)MROWS*EM];
__device__ float g_e [(size_t)NBH*SQ*SQ];
__device__ float g_lp[(size_t)NBH*SQ*16];
__device__ float g_main[(size_t)MROWS*EM];

/* ============================ helpers ============================ */
__device__ __forceinline__ void split2(float x, float y, uint32_t& h, uint32_t& l) {
    __nv_bfloat162 hv = __floats2bfloat162_rn(x, y);
    float rx = x - __bfloat162float(__low2bfloat16(hv));
    float ry = y - __bfloat162float(__high2bfloat16(hv));
    __nv_bfloat162 lv = __floats2bfloat162_rn(rx, ry);
    h = *reinterpret_cast<uint32_t*>(&hv);
    l = *reinterpret_cast<uint32_t*>(&lv);
}

__device__ __forceinline__ void mma_bf16(float* d, const uint32_t* a, const uint32_t* b) {
    asm volatile(
        "mma.sync.aligned.m16n8k16.row.col.f32.bf16.bf16.f32 "
        "{%0,%1,%2,%3}, {%4,%5,%6,%7}, {%8,%9}, {%0,%1,%2,%3};"
        : "+f"(d[0]), "+f"(d[1]), "+f"(d[2]), "+f"(d[3])
        : "r"(a[0]), "r"(a[1]), "r"(a[2]), "r"(a[3]), "r"(b[0]), "r"(b[1]));
}

#define LDMX4(r, a)                                                          \
    asm volatile("ldmatrix.sync.aligned.m8n8.x4.shared.b16 {%0,%1,%2,%3}, [%4];" \
        : "=r"((r)[0]), "=r"((r)[1]), "=r"((r)[2]), "=r"((r)[3]) : "r"(a))

__device__ __forceinline__ void cp16(uint32_t dst, const void* src) {
    asm volatile("cp.async.cg.shared.global [%0], [%1], 16;" :: "r"(dst), "l"(src));
}
#define CP_COMMIT() asm volatile("cp.async.commit_group;" ::: "memory")
#define CP_WAIT0()  asm volatile("cp.async.wait_group 0;" ::: "memory")
#define CP_WAIT1()  asm volatile("cp.async.wait_group 1;" ::: "memory")

__device__ __forceinline__ uint32_t smem_u32(const void* p) {
    return (uint32_t)__cvta_generic_to_shared(const_cast<void*>(p));
}

/* warp computes (MT*16)m x (NT*8)n over KC k16-groups; 3xBF16 split.
 * RB = smem row stride in bytes. warps: wm in {0,1}, wn in {0..3}. */
template<int MT, int NT, int RB, int KC>
__device__ __forceinline__ void compute_tile(
    float acc[][4], uint32_t Ah, uint32_t Al, uint32_t Bh, uint32_t Bl,
    int wm, int wn, int lid)
{
    const int arow = lid & 15;
    const int ak   = (lid >> 4) * 16;
    const int brow = (lid & 7) + ((lid >> 4) & 1) * 8;
    const int bk   = ((lid >> 3) & 1) * 16;
#pragma unroll
    for (int kc = 0; kc < KC; ++kc) {
        uint32_t aH[MT][4], aL[MT][4];
#pragma unroll
        for (int mt = 0; mt < MT; ++mt) {
            uint32_t off = (uint32_t)(wm * (MT * 16) + mt * 16 + arow) * RB + kc * 32 + ak;
            LDMX4(aH[mt], Ah + off);
            LDMX4(aL[mt], Al + off);
        }
#pragma unroll
        for (int np = 0; np < NT / 2; ++np) {
            uint32_t boff = (uint32_t)(wn * (NT * 8) + np * 16 + brow) * RB + kc * 32 + bk;
            uint32_t bH[4], bL[4];
            LDMX4(bH, Bh + boff);
            LDMX4(bL, Bl + boff);
#pragma unroll
            for (int half = 0; half < 2; ++half) {
                int nt = np * 2 + half;
                uint32_t* bh = bH + half * 2;
                uint32_t* bl = bL + half * 2;
#pragma unroll
                for (int mt = 0; mt < MT; ++mt) {
                    mma_bf16(acc[mt * NT + nt], aH[mt], bh);
                    mma_bf16(acc[mt * NT + nt], aH[mt], bl);
                    mma_bf16(acc[mt * NT + nt], aL[mt], bh);
                }
            }
        }
    }
}

/* ============================================================
 * split_inputs / transpose_w  (prep)
 * ============================================================ */
__global__ __launch_bounds__(256) void split_inputs(
    const float* q, const float* k, const float* kg, const float* v,
    __nv_bfloat16* hi, __nv_bfloat16* lo)
{
    const float* S;
    if (blockIdx.y == 0) S = q; else if (blockIdx.y == 1) S = k;
    else if (blockIdx.y == 2) S = kg; else S = v;
    size_t off = (size_t)blockIdx.y * MROWS * EM;
    size_t i = (size_t)blockIdx.x * 256 + threadIdx.x;
    float4 x = ((const float4*)S)[i];
    uint32_t h0, l0, h1, l1;
    split2(x.x, x.y, h0, l0);
    split2(x.z, x.w, h1, l1);
    *(uint2*)(hi + off + i * 4) = make_uint2(h0, h1);
    *(uint2*)(lo + off + i * 4) = make_uint2(l0, l1);
}

__global__ __launch_bounds__(256) void transpose_w(
    const float* W0, const float* W1, const float* W2,
    const float* W3, const float* W4,
    __nv_bfloat16* outhi, __nv_bfloat16* outlo)
{
    const float* W;
    if (blockIdx.z == 0) W = W0; else if (blockIdx.z == 1) W = W1;
    else if (blockIdx.z == 2) W = W2; else if (blockIdx.z == 3) W = W3; else W = W4;
    size_t off = (size_t)blockIdx.z * EM * EM;
    __shared__ float t[32][33];
    int tx = threadIdx.x, ty = threadIdx.y;
    int x = blockIdx.x * 32 + tx;
    int y0 = blockIdx.y * 32;
    for (int i = ty; i < 32; i += 8)
        t[i][tx] = W[(size_t)(y0 + i) * EM + x];
    __syncthreads();
    int xo = blockIdx.y * 32 + tx;
    int yo0 = blockIdx.x * 32;
    for (int i = ty; i < 32; i += 8) {
        float val = t[tx][i];
        __nv_bfloat16 h = __float2bfloat16(val);
        float r = val - __bfloat162float(h);
        size_t idx = off + (size_t)(yo0 + i) * EM + xo;
        outhi[idx] = h;
        outlo[idx] = __float2bfloat16(r);
    }
}

/* ============================================================
 * proj_body: BM=64, BN=128, BK=32; 2-stage cp.async pipeline
 * stage layout: [Ah 5120][Al 5120][Bh 10240][Bl 10240] = 30720
 * ============================================================ */
#define PJ_STGB 30720

__device__ __forceinline__ void proj_body(
    uint32_t* smw,
    const __nv_bfloat16* A1h, const __nv_bfloat16* A1l,
    const __nv_bfloat16* A2h, const __nv_bfloat16* A2l,
    const __nv_bfloat16* W1h, const __nv_bfloat16* W1l,
    const __nv_bfloat16* W2h, const __nv_bfloat16* W2l,
    const float* b1, const float* b2,
    float* outf, __nv_bfloat16* outhi, __nv_bfloat16* outlo,
    int mode, int n0, int m0)
{
    const int tid = threadIdx.x, wid = tid >> 5, lid = tid & 31;
    const int wm = wid & 1, wn = wid >> 1, grp = lid >> 2, tig = lid & 3;
    const uint32_t smb = smem_u32(smw);
    const int LDB = EM * 2;

    float acc[8][4];
#pragma unroll
    for (int i = 0; i < 8; ++i)
#pragma unroll
        for (int j = 0; j < 4; ++j) acc[i][j] = 0.f;

    const int CPP = EM / 32;
    const int NCH = (A2h ? 2 : 1) * CPP;

    auto issue = [&](int slot, int c) {
        int pass = (c >= CPP);
        int k0b = (c - pass * CPP) * 64;
        const char* sAh = (const char*)(pass ? A2h : A1h) + (size_t)m0 * LDB;
        const char* sAl = (const char*)(pass ? A2l : A1l) + (size_t)m0 * LDB;
        const char* sWh = (const char*)(pass ? W2h : W1h) + (size_t)n0 * LDB;
        const char* sWl = (const char*)(pass ? W2l : W1l) + (size_t)n0 * LDB;
        uint32_t base = smb + (uint32_t)slot * PJ_STGB;
#pragma unroll
        for (int it = 0; it < 6; ++it) {
            int t = tid + it * 256;
            const char* sp;
            uint32_t doff;
            int row, seg;
            if (t < 512) {
                int buf = t >> 8, e = t & 255;
                row = e >> 2; seg = e & 3;
                sp = buf ? sAl : sAh;
                doff = (uint32_t)buf * 5120 + row * 80 + seg * 16;
            } else {
                int e = t - 512;
                int buf = e >> 9; e &= 511;
                row = e >> 2; seg = e & 3;
                sp = buf ? sWl : sWh;
                doff = 10240u + (uint32_t)buf * 10240 + row * 80 + seg * 16;
            }
            cp16(base + doff, sp + (size_t)row * LDB + k0b + seg * 16);
        }
    };

    issue(0, 0); CP_COMMIT();
    issue(1, 1); CP_COMMIT();
    for (int c = 0; c < NCH; ++c) {
        CP_WAIT1();
        __syncthreads();
        uint32_t cb = smb + (uint32_t)(c & 1) * PJ_STGB;
        compute_tile<2, 4, 80, 2>(acc, cb, cb + 5120, cb + 10240, cb + 20480,
                                  wm, wn, lid);
        __syncthreads();
        if (c + 2 < NCH) issue(c & 1, c + 2);
        CP_COMMIT();
    }

    float* Csm = (float*)smw;
    const int CS = 132;
#pragma unroll
    for (int mt = 0; mt < 2; ++mt)
#pragma unroll
        for (int nt = 0; nt < 4; ++nt) {
            int row = wm * 32 + mt * 16 + grp, col = wn * 32 + nt * 8 + tig * 2;
            float* a = acc[mt * 4 + nt];
            *(float2*)&Csm[row * CS + col]       = make_float2(a[0], a[1]);
            *(float2*)&Csm[(row + 8) * CS + col] = make_float2(a[2], a[3]);
        }
    __syncthreads();

    if (mode == 2) {
        int b = m0 >> 11, sbase = m0 & (SQ - 1);
#pragma unroll
        for (int it = 0; it < 8; ++it) {
            int e = tid + it * 256;             /* 128 cols x 16 s-groups */
            int col = e >> 4, sb = e & 15;
            int nn = n0 + col;
            float bias = b1[nn];
            float4 v;
            v.x = Csm[(sb * 4 + 0) * CS + col] + bias;
            v.y = Csm[(sb * 4 + 1) * CS + col] + bias;
            v.z = Csm[(sb * 4 + 2) * CS + col] + bias;
            v.w = Csm[(sb * 4 + 3) * CS + col] + bias;
            int hh = nn >> 6, d = nn & 63;
            size_t idx = (((size_t)(b * NH + hh)) * DH + d) * SQ + sbase + sb * 4;
            uint32_t h0, l0, h1, l1;
            split2(v.x, v.y, h0, l0);
            split2(v.z, v.w, h1, l1);
            *(uint2*)(outhi + idx) = make_uint2(h0, h1);
            *(uint2*)(outlo + idx) = make_uint2(l0, l1);
        }
    } else {
#pragma unroll
        for (int it = 0; it < 8; ++it) {
            int e = tid + it * 256;
            int row = e >> 5, c4 = (e & 31) * 4;
            int m = m0 + row, n = n0 + c4;
            float4 v = *(float4*)&Csm[row * CS + c4];
            v.x += b1[n + 0]; v.y += b1[n + 1]; v.z += b1[n + 2]; v.w += b1[n + 3];
            if (b2) { v.x += b2[n + 0]; v.y += b2[n + 1]; v.z += b2[n + 2]; v.w += b2[n + 3]; }
            if (mode == 1) {
                int b = m >> 11, sA = m & (SQ - 1);
                int hh = n >> 6, d = n & 63;
                size_t idx = (((size_t)(b * NH + hh)) * SQ + sA) * DH + d;
                uint32_t h0, l0, h1, l1;
                split2(v.x, v.y, h0, l0);
                split2(v.z, v.w, h1, l1);
                *(uint2*)(outhi + idx) = make_uint2(h0, h1);
                *(uint2*)(outlo + idx) = make_uint2(l0, l1);
            } else {
                *(float4*)(outf + (size_t)m * EM + n) = v;
            }
        }
    }
}

__global__ __launch_bounds__(256, 3) void proj_qkv(
    const __nv_bfloat16* Ahi, const __nv_bfloat16* Alo,
    const __nv_bfloat16* Whi, const __nv_bfloat16* Wlo,
    const float* bq, const float* bk, const float* bkg, const float* bv,
    __nv_bfloat16* Qhi, __nv_bfloat16* Qlo,
    __nv_bfloat16* Khi, __nv_bfloat16* Klo,
    __nv_bfloat16* Vthi, __nv_bfloat16* Vtlo)
{
    extern __shared__ uint32_t smw[];
    const int n0 = blockIdx.x * 128, m0 = blockIdx.y * 64;
    const size_t AT = (size_t)MROWS * EM, WT = (size_t)EM * EM;
    if (blockIdx.z == 0)
        proj_body(smw, Ahi, Alo, nullptr, nullptr, Whi, Wlo, nullptr, nullptr,
                  bq, nullptr, nullptr, Qhi, Qlo, 1, n0, m0);
    else if (blockIdx.z == 1)
        proj_body(smw, Ahi + AT, Alo + AT, Ahi + 2*AT, Alo + 2*AT,
                  Whi + WT, Wlo + WT, Whi + 2*WT, Wlo + 2*WT,
                  bk, bkg, nullptr, Khi, Klo, 1, n0, m0);
    else
        proj_body(smw, Ahi + 3*AT, Alo + 3*AT, nullptr, nullptr,
                  Whi + 3*WT, Wlo + 3*WT, nullptr, nullptr,
                  bv, nullptr, nullptr, Vthi, Vtlo, 2, n0, m0);
}

__global__ __launch_bounds__(256, 3) void proj_o(
    const __nv_bfloat16* Ohi, const __nv_bfloat16* Olo,
    const __nv_bfloat16* Whi, const __nv_bfloat16* Wlo,
    const float* bo, float* C)
{
    extern __shared__ uint32_t smw[];
    const size_t WT = (size_t)EM * EM;
    proj_body(smw, Ohi, Olo, nullptr, nullptr, Whi + 4*WT, Wlo + 4*WT,
              nullptr, nullptr, bo, nullptr, C, nullptr, nullptr, 0,
              blockIdx.x * 128, blockIdx.y * 64);
}

/* ============================================================
 * qk_mma: BM=64, BN=128, K=64 single-shot
 * smem: [Qh 9216][Ql 9216][Kh 18432][Kl 18432] = 55296
 * ============================================================ */
__global__ __launch_bounds__(256, 3) void qk_mma(
    const __nv_bfloat16* Qhi, const __nv_bfloat16* Qlo,
    const __nv_bfloat16* Khi, const __nv_bfloat16* Klo,
    const int* __restrict__ mask, float* __restrict__ e_out,
    float* __restrict__ lp)
{
    extern __shared__ uint32_t smw[];
    const int tid = threadIdx.x, wid = tid >> 5, lid = tid & 31;
    const int n0 = blockIdx.x * 128, m0 = blockIdx.y * 64;
    const int bh = blockIdx.z, b = bh / NH;
    const int wm = wid & 1, wn = wid >> 1, grp = lid >> 2, tig = lid & 3;
    const uint32_t smb = smem_u32(smw);
    const char* sQh = (const char*)Qhi + ((size_t)bh * SQ + m0) * 128;
    const char* sQl = (const char*)Qlo + ((size_t)bh * SQ + m0) * 128;
    const char* sKh = (const char*)Khi + ((size_t)bh * SQ + n0) * 128;
    const char* sKl = (const char*)Klo + ((size_t)bh * SQ + n0) * 128;

#pragma unroll
    for (int it = 0; it < 12; ++it) {
        int t = tid + it * 256;
        const char* sp;
        uint32_t doff;
        int row, seg;
        if (t < 1024) {
            int buf = t >> 9, e = t & 511;
            row = e >> 3; seg = e & 7;
            sp = buf ? sQl : sQh;
            doff = (uint32_t)buf * 9216 + row * 144 + seg * 16;
        } else {
            int e = t - 1024;
            int buf = e >> 10; e &= 1023;
            row = e >> 3; seg = e & 7;
            sp = buf ? sKl : sKh;
            doff = 18432u + (uint32_t)buf * 18432 + row * 144 + seg * 16;
        }
        cp16(smb + doff, sp + (size_t)row * 128 + seg * 16);
    }
    CP_COMMIT();
    CP_WAIT0();
    __syncthreads();

    float acc[8][4];
#pragma unroll
    for (int i = 0; i < 8; ++i)
#pragma unroll
        for (int j = 0; j < 4; ++j) acc[i][j] = 0.f;

    compute_tile<2, 4, 144, 4>(acc, smb, smb + 9216, smb + 18432, smb + 36864,
                               wm, wn, lid);
    __syncthreads();

    float* Csm = (float*)smw;
    const int CS = 132;
#pragma unroll
    for (int mt = 0; mt < 2; ++mt)
#pragma unroll
        for (int nt = 0; nt < 4; ++nt) {
            int row = wm * 32 + mt * 16 + grp, col = wn * 32 + nt * 8 + tig * 2;
            float* a = acc[mt * 4 + nt];
            *(float2*)&Csm[row * CS + col]       = make_float2(a[0], a[1]);
            *(float2*)&Csm[(row + 8) * CS + col] = make_float2(a[2], a[3]);
        }
    __syncthreads();

    const int* mb = mask + (size_t)b * SQ * SQ;
    float* eb = e_out + (size_t)bh * SQ * SQ;
#pragma unroll 1
    for (int it = 0; it < 8; ++it) {
        int eidx = tid + it * 256;
        int row = eidx >> 5, c4 = (eidx & 31) * 4;
        int m = m0 + row, n = n0 + c4;
        float4 v = *(float4*)&Csm[row * CS + c4];
        int4 mk = *(const int4*)(mb + (size_t)m * SQ + n);
        v.x = mk.x ? __expf(v.x * 0.125f) : 0.f;
        v.y = mk.y ? __expf(v.y * 0.125f) : 0.f;
        v.z = mk.z ? __expf(v.z * 0.125f) : 0.f;
        v.w = mk.w ? __expf(v.w * 0.125f) : 0.f;
        *(float4*)(eb + (size_t)m * SQ + n) = v;
        float s4 = v.x + v.y + v.z + v.w;
#pragma unroll
        for (int o = 16; o; o >>= 1) s4 += __shfl_xor_sync(0xffffffffu, s4, o);
        if (lid == 0)
            lp[((size_t)bh * SQ + m) * 16 + blockIdx.x] = s4;
    }
}

/* ============================================================
 * av_mma: BM=64, BN=64; normalizes e, writes attn, O = attn@V
 * stage: [Ph 5120][Pl 5120][Vh 5120][Vl 5120] = 20480; x2 + invl
 * ============================================================ */
#define AV_STGB 20480

__global__ __launch_bounds__(256, 3) void av_mma(
    const float* __restrict__ e_in, const float* __restrict__ lp,
    const __nv_bfloat16* Vhi, const __nv_bfloat16* Vlo,
    float* __restrict__ attn, __nv_bfloat16* Ohi, __nv_bfloat16* Olo)
{
    extern __shared__ uint32_t smw[];
    const int tid = threadIdx.x, wid = tid >> 5, lid = tid & 31;
    const int m0 = blockIdx.x * 64;
    const int bh = blockIdx.y, b = bh / NH, hh = bh % NH;
    const int wm = wid & 1, wn = wid >> 1, grp = lid >> 2, tig = lid & 3;
    const uint32_t smb = smem_u32(smw);
    const float* Pb = e_in + (size_t)bh * SQ * SQ + (size_t)m0 * SQ;
    float* attnb = attn + (size_t)bh * SQ * SQ + (size_t)m0 * SQ;
    const char* Vh = (const char*)Vhi + (size_t)bh * DH * SQ * 2;
    const char* Vl = (const char*)Vlo + (size_t)bh * DH * SQ * 2;
    float* invl = (float*)((char*)smw + 2 * AV_STGB);

    if (tid < 64) {
        const float* q = lp + ((size_t)bh * SQ + m0 + tid) * 16;
        float s = 0.f;
#pragma unroll
        for (int i = 0; i < 16; ++i) s += q[i];
        invl[tid] = 1.f / fmaxf(s, 1e-30f);
    }
    __syncthreads();

    float acc[4][4];
#pragma unroll
    for (int i = 0; i < 4; ++i)
#pragma unroll
        for (int j = 0; j < 4; ++j) acc[i][j] = 0.f;

    const int vrow = tid >> 2, vseg = tid & 3;

    auto ldgP = [&](int k0, float4* v) {
#pragma unroll
        for (int p = 0; p < 2; ++p) {
            int i = tid + p * 256, r = i >> 3, c = i & 7;
            v[p] = *(const float4*)(Pb + (size_t)r * SQ + k0 + c * 4);
        }
    };
    auto stsP = [&](int slot, const float4* v, int k0) {
        uint32_t* H = smw + slot * (AV_STGB / 4);
        uint32_t* L = H + 1280;
#pragma unroll
        for (int p = 0; p < 2; ++p) {
            int i = tid + p * 256, r = i >> 3, c = i & 7;
            float il = invl[r];
            float4 w;
            w.x = v[p].x * il; w.y = v[p].y * il;
            w.z = v[p].z * il; w.w = v[p].w * il;
            *(float4*)(attnb + (size_t)r * SQ + k0 + c * 4) = w;
            uint32_t h0, l0, h1, l1;
            split2(w.x, w.y, h0, l0);
            split2(w.z, w.w, h1, l1);
            int bw = r * 20 + c * 2;
            *(uint2*)&H[bw] = make_uint2(h0, h1);
            *(uint2*)&L[bw] = make_uint2(l0, l1);
        }
    };
    auto ldgV = [&](int k0b, uint4& h, uint4& l) {
        size_t o = (size_t)vrow * (SQ * 2) + k0b + vseg * 16;
        h = *(const uint4*)(Vh + o);
        l = *(const uint4*)(Vl + o);
    };
    auto stsV = [&](int slot, uint4 vh, uint4 vl) {
        char* base = (char*)smw + slot * AV_STGB + 10240;
        *(uint4*)(base + vrow * 80 + vseg * 16) = vh;
        *(uint4*)(base + 5120 + vrow * 80 + vseg * 16) = vl;
    };

    float4 va[2];
    uint4 vh, vl;
    ldgP(0, va);
    ldgV(0, vh, vl);
    stsP(0, va, 0);
    stsV(0, vh, vl);
    __syncthreads();

    const int NCH = SQ / 32;
    for (int c = 0; c < NCH; ++c) {
        bool more = (c + 1 < NCH);
        if (more) {
            ldgP((c + 1) * 32, va);
            ldgV((c + 1) * 64, vh, vl);
        }
        uint32_t cb = smb + (uint32_t)(c & 1) * AV_STGB;
        compute_tile<2, 2, 80, 2>(acc, cb, cb + 5120, cb + 10240, cb + 15360,
                                  wm, wn, lid);
        __syncthreads();
        if (more) {
            stsP((c + 1) & 1, va, (c + 1) * 32);
            stsV((c + 1) & 1, vh, vl);
        }
        __syncthreads();
    }

    float* Csm = (float*)smw;
    const int CS = 68;
#pragma unroll
    for (int mt = 0; mt < 2; ++mt)
#pragma unroll
        for (int nt = 0; nt < 2; ++nt) {
            int row = wm * 32 + mt * 16 + grp, col = wn * 16 + nt * 8 + tig * 2;
            float* a = acc[mt * 2 + nt];
            *(float2*)&Csm[row * CS + col]       = make_float2(a[0], a[1]);
            *(float2*)&Csm[(row + 8) * CS + col] = make_float2(a[2], a[3]);
        }
    __syncthreads();

#pragma unroll
    for (int it = 0; it < 4; ++it) {
        int e = tid + it * 256;
        int row = e >> 4, c4 = (e & 15) * 4;
        float4 v = *(float4*)&Csm[row * CS + c4];
        size_t idx = (size_t)(b * SQ + m0 + row) * EM + hh * DH + c4;
        uint32_t h0, l0, h1, l1;
        split2(v.x, v.y, h0, l0);
        split2(v.z, v.w, h1, l1);
        *(uint2*)(Ohi + idx) = make_uint2(h0, h1);
        *(uint2*)(Olo + idx) = make_uint2(l0, l1);
    }
}

/* ===================================================================== */
extern "C" void kernel_launch(void* const* d_in, const int* in_sizes, int n_in,
                              void* d_out, int out_size)
{
    (void)in_sizes; (void)n_in;
    const float* query = (const float*)d_in[0];
    const float* key   = (const float*)d_in[1];
    const float* value = (const float*)d_in[2];
    const float* kginf = (const float*)d_in[3];
    const int*   mask  = (const int*)d_in[4];
    const float* Wq  = (const float*)d_in[5];  const float* bq  = (const float*)d_in[6];
    const float* Wk  = (const float*)d_in[7];  const float* bk  = (const float*)d_in[8];
    const float* Wv  = (const float*)d_in[9];  const float* bv  = (const float*)d_in[10];
    const float* Wkg = (const float*)d_in[11]; const float* bkg = (const float*)d_in[12];
    const float* Wo  = (const float*)d_in[13]; const float* bo  = (const float*)d_in[14];

    __nv_bfloat16 *ahi, *alo, *whi, *wlo, *qhi, *qlo, *khi, *klo, *vthi, *vtlo, *ohi, *olo;
    float *ge, *glp, *gmain;
    cudaGetSymbolAddress((void**)&ahi,  g_Ahi);
    cudaGetSymbolAddress((void**)&alo,  g_Alo);
    cudaGetSymbolAddress((void**)&whi,  g_Wthi);
    cudaGetSymbolAddress((void**)&wlo,  g_Wtlo);
    cudaGetSymbolAddress((void**)&qhi,  g_Qhi);
    cudaGetSymbolAddress((void**)&qlo,  g_Qlo);
    cudaGetSymbolAddress((void**)&khi,  g_Khi);
    cudaGetSymbolAddress((void**)&klo,  g_Klo);
    cudaGetSymbolAddress((void**)&vthi, g_Vthi);
    cudaGetSymbolAddress((void**)&vtlo, g_Vtlo);
    cudaGetSymbolAddress((void**)&ohi,  g_Ohi);
    cudaGetSymbolAddress((void**)&olo,  g_Olo);
    cudaGetSymbolAddress((void**)&ge,   g_e);
    cudaGetSymbolAddress((void**)&glp,  g_lp);
    cudaGetSymbolAddress((void**)&gmain, g_main);

    const long long MAIN = (long long)MROWS * EM;
    const long long ATTN = (long long)NBH * SQ * SQ;
    float* out = (float*)d_out;
    float* main_out;
    float* attn;
    long long osz = (long long)out_size;
    if (osz >= MAIN + ATTN)      { main_out = out; attn = out + MAIN; }
    else if (osz >= ATTN)        { attn = out; main_out = gmain; }
    else                         { main_out = out; attn = ge; }

    const int PJ_SMEM = 2 * PJ_STGB;           /* 61440 */
    const int QK_SMEM = 55296;
    const int AV_SMEM = 2 * AV_STGB + 256;     /* 41216 */
    cudaFuncSetAttribute(proj_qkv, cudaFuncAttributeMaxDynamicSharedMemorySize, PJ_SMEM);
    cudaFuncSetAttribute(proj_o,   cudaFuncAttributeMaxDynamicSharedMemorySize, PJ_SMEM);
    cudaFuncSetAttribute(qk_mma,   cudaFuncAttributeMaxDynamicSharedMemorySize, QK_SMEM);
    cudaFuncSetAttribute(av_mma,   cudaFuncAttributeMaxDynamicSharedMemorySize, AV_SMEM);

    dim3 blk(256);
    split_inputs<<<dim3(MROWS * EM / 4 / 256, 4), blk>>>(query, key, kginf, value, ahi, alo);
    transpose_w<<<dim3(EM/32, EM/32, 5), dim3(32, 8)>>>(Wq, Wk, Wkg, Wv, Wo, whi, wlo);

    proj_qkv<<<dim3(EM/128, MROWS/64, 3), blk, PJ_SMEM>>>(
        ahi, alo, whi, wlo, bq, bk, bkg, bv, qhi, qlo, khi, klo, vthi, vtlo);

    qk_mma<<<dim3(SQ/128, SQ/64, NBH), blk, QK_SMEM>>>(
        qhi, qlo, khi, klo, mask, ge, glp);

    av_mma<<<dim3(SQ/64, NBH), blk, AV_SMEM>>>(
        ge, glp, vthi, vtlo, attn, ohi, olo);

    proj_o<<<dim3(EM/128, MROWS/64), blk, PJ_SMEM>>>(ohi, olo, whi, wlo, bo, main_out);
}